// round 12
// baseline (speedup 1.0000x reference)
#include <cuda_runtime.h>
#include <cuda_fp16.h>
#include <math.h>
#include <stdint.h>

// ---------------- problem sizes ----------------
#define NA 50000
#define NP 100000
#define HC 128
#define NH 8
#define EW 400000
#define ER 400000
#define EC 800000
#define EP (EW + EC)
#define BN_EPS 1e-5f

// ---------------- scratch layout (float units) ----------------
#define OFF_XA    0ull
#define OFF_XP    (OFF_XA   + (size_t)NA*128)
#define OFF_QA    (OFF_XP   + (size_t)NP*128)
#define OFF_QP    (OFF_QA   + (size_t)NA*128)
#define OFF_KVP   (OFF_QP   + (size_t)NP*128)        // half[(NA+NP)*256]
#define OFF_KVA   (OFF_KVP  + (size_t)(NA+NP)*128)   // half[NP*256]
#define OFF_AGGA  (OFF_KVA  + (size_t)NP*128)
#define OFF_AGGP  (OFF_AGGA + (size_t)NA*128)
#define OFF_TMPA  (OFF_AGGP + (size_t)NP*128)
#define OFF_TMPP  (OFF_TMPA + (size_t)NA*128)
#define OFF_WC    (OFF_TMPP + (size_t)NP*128)        // 6 * 128 * 256 composite KV weights
#define OFF_WCB   (OFF_WC   + 6ull*128*256)          // 6 * 256 composite biases
#define OFF_STATS (OFF_WCB  + 6ull*256)
// integer region
#define OFF_INT   (OFF_STATS + 512ull)
#define IOFF_ROWP 0ull
#define IOFF_ROWA (IOFF_ROWP + NP + 1)
#define IOFF_CURP (IOFF_ROWA + NA + 1)
#define IOFF_CURA (IOFF_CURP + NP)
#define IOFF_SRCP (IOFF_CURA + NA)
#define IOFF_SRCA (IOFF_SRCP + EP)
#define IOFF_BS   (IOFF_SRCA + ER)
#define INT_TOTAL (IOFF_BS + 256)
#define TOTAL_FLOATS (OFF_INT + INT_TOTAL + 64ull)

__device__ float g_scratch[TOTAL_FLOATS];

// ---------------- tf32 helpers ----------------
__device__ __forceinline__ uint32_t f2tf32(float x)
{
    uint32_t r;
    asm("cvt.rna.tf32.f32 %0, %1;" : "=r"(r) : "f"(x));
    return r;
}

__device__ __forceinline__ void mma_tf32(float4& c, const uint32_t* a, const uint32_t* b)
{
    asm volatile(
        "mma.sync.aligned.m16n8k8.row.col.f32.tf32.tf32.f32 "
        "{%0,%1,%2,%3}, {%4,%5,%6,%7}, {%8,%9}, {%0,%1,%2,%3};"
        : "+f"(c.x), "+f"(c.y), "+f"(c.z), "+f"(c.w)
        : "r"(a[0]), "r"(a[1]), "r"(a[2]), "r"(a[3]), "r"(b[0]), "r"(b[1]));
}

// ---------------- tf32x2 tensor-core GEMM (EXACT R8 form; lean epilogue) --------
// C[M, gridN] = A[M,K] @ W[K,*] + bias. BM=128, BN=128, BK=16, 8 warps 2x4.
// Ch != nullptr -> half output (C ignored). act: 0=none, 1=relu, 2=skip-mix
__global__ void __launch_bounds__(256)
gemm_tf32(const float* __restrict__ A, int lda, const float* __restrict__ W, int ldw,
          const float* __restrict__ bias, float* __restrict__ C, __half* __restrict__ Ch,
          int ldc, int M, int K, int act,
          const float* __restrict__ xold, const float* __restrict__ skipv)
{
    __shared__ uint32_t As[128][20];
    __shared__ uint32_t Bs[16][136], Bl[16][136];

    const int bm = blockIdx.y * 128;
    const int bn = blockIdx.x * 128;
    const int tid = threadIdx.x;
    const int lane = tid & 31;
    const int warp = tid >> 5;
    const int wm = warp >> 2;
    const int wn = warp & 3;

    float4 acc[4][4];
#pragma unroll
    for (int i = 0; i < 4; i++)
#pragma unroll
        for (int j = 0; j < 4; j++) acc[i][j] = make_float4(0.f, 0.f, 0.f, 0.f);

    for (int k0 = 0; k0 < K; k0 += 16) {
#pragma unroll
        for (int i = 0; i < 2; i++) {
            int id  = tid + i * 256;
            int row = id >> 2;
            int kc  = (id & 3) * 4;
            int grow = bm + row;
            float4 v = make_float4(0.f, 0.f, 0.f, 0.f);
            if (grow < M) v = *(const float4*)(A + (size_t)grow * lda + k0 + kc);
            As[row][kc + 0] = f2tf32(v.x); As[row][kc + 1] = f2tf32(v.y);
            As[row][kc + 2] = f2tf32(v.z); As[row][kc + 3] = f2tf32(v.w);
        }
#pragma unroll
        for (int i = 0; i < 2; i++) {
            int id  = tid + i * 256;
            int row = id >> 5;
            int col = (id & 31) * 4;
            float4 v = *(const float4*)(W + (size_t)(k0 + row) * ldw + bn + col);
            uint32_t h;
            h = f2tf32(v.x); Bs[row][col + 0] = h; Bl[row][col + 0] = f2tf32(v.x - __uint_as_float(h));
            h = f2tf32(v.y); Bs[row][col + 1] = h; Bl[row][col + 1] = f2tf32(v.y - __uint_as_float(h));
            h = f2tf32(v.z); Bs[row][col + 2] = h; Bl[row][col + 2] = f2tf32(v.z - __uint_as_float(h));
            h = f2tf32(v.w); Bs[row][col + 3] = h; Bl[row][col + 3] = f2tf32(v.w - __uint_as_float(h));
        }
        __syncthreads();

#pragma unroll
        for (int ks = 0; ks < 16; ks += 8) {
            uint32_t af[4][4];
            const int kc = ks + (lane & 3);
#pragma unroll
            for (int mf = 0; mf < 4; mf++) {
                int r = wm * 64 + mf * 16 + (lane >> 2);
                af[mf][0] = As[r][kc];
                af[mf][1] = As[r + 8][kc];
                af[mf][2] = As[r][kc + 4];
                af[mf][3] = As[r + 8][kc + 4];
            }
            uint32_t bh[4][2], bl[4][2];
#pragma unroll
            for (int nf = 0; nf < 4; nf++) {
                int n = wn * 32 + nf * 8 + (lane >> 2);
                bh[nf][0] = Bs[kc][n];     bl[nf][0] = Bl[kc][n];
                bh[nf][1] = Bs[kc + 4][n]; bl[nf][1] = Bl[kc + 4][n];
            }
#pragma unroll
            for (int mf = 0; mf < 4; mf++)
#pragma unroll
                for (int nf = 0; nf < 4; nf++) {
                    mma_tf32(acc[mf][nf], af[mf], bl[nf]);
                    mma_tf32(acc[mf][nf], af[mf], bh[nf]);
                }
        }
        __syncthreads();
    }

    const int lr = lane >> 2;
    const int lc = (lane & 3) * 2;
    float sk = 0.f;
    if (act == 2) sk = 1.f / (1.f + __expf(-skipv[0]));
    float2 bv[4];
#pragma unroll
    for (int nf = 0; nf < 4; nf++) {
        int c0 = bn + wn * 32 + nf * 8 + lc;
        bv[nf] = *(const float2*)(bias + c0);
    }
#pragma unroll
    for (int mf = 0; mf < 4; mf++) {
        int r0 = bm + wm * 64 + mf * 16 + lr;
        int r1 = r0 + 8;
#pragma unroll
        for (int nf = 0; nf < 4; nf++) {
            int c0 = bn + wn * 32 + nf * 8 + lc;
            float4 a = acc[mf][nf];
            float2 o0 = make_float2(a.x + bv[nf].x, a.y + bv[nf].y);
            float2 o1 = make_float2(a.z + bv[nf].x, a.w + bv[nf].y);
            if (act == 1) {
                o0.x = fmaxf(o0.x, 0.f); o0.y = fmaxf(o0.y, 0.f);
                o1.x = fmaxf(o1.x, 0.f); o1.y = fmaxf(o1.y, 0.f);
            } else if (act == 2) {
                if (r0 < M) {
                    float2 x0 = *(const float2*)(xold + (size_t)r0 * ldc + c0);
                    o0.x = sk * o0.x + (1.f - sk) * x0.x;
                    o0.y = sk * o0.y + (1.f - sk) * x0.y;
                }
                if (r1 < M) {
                    float2 x1 = *(const float2*)(xold + (size_t)r1 * ldc + c0);
                    o1.x = sk * o1.x + (1.f - sk) * x1.x;
                    o1.y = sk * o1.y + (1.f - sk) * x1.y;
                }
            }
            if (Ch) {
                if (r0 < M) *(__half2*)(Ch + (size_t)r0 * ldc + c0) = __floats2half2_rn(o0.x, o0.y);
                if (r1 < M) *(__half2*)(Ch + (size_t)r1 * ldc + c0) = __floats2half2_rn(o1.x, o1.y);
            } else {
                if (r0 < M) *(float2*)(C + (size_t)r0 * ldc + c0) = o0;
                if (r1 < M) *(float2*)(C + (size_t)r1 * ldc + c0) = o1;
            }
        }
    }
}

// ---------------- dedicated out-projection GEMM: skip-mix + fused BN stats ------
// Identical mainloop to gemm_tf32; used ONLY by the 2 out-proj launches.
// Single column tile (grid.x==1): channel == local column.
__global__ void __launch_bounds__(256)
gemm_out(const float* __restrict__ A, const float* __restrict__ W,
         const float* __restrict__ bias, float* __restrict__ C,
         int M, const float* __restrict__ xold, const float* __restrict__ skipv,
         float* __restrict__ stats)
{
    __shared__ uint32_t As[128][20];
    __shared__ uint32_t Bs[16][136], Bl[16][136];
    __shared__ float bnS[256];

    const int bm = blockIdx.y * 128;
    const int tid = threadIdx.x;
    const int lane = tid & 31;
    const int warp = tid >> 5;
    const int wm = warp >> 2;
    const int wn = warp & 3;

    float4 acc[4][4];
#pragma unroll
    for (int i = 0; i < 4; i++)
#pragma unroll
        for (int j = 0; j < 4; j++) acc[i][j] = make_float4(0.f, 0.f, 0.f, 0.f);

    for (int k0 = 0; k0 < 128; k0 += 16) {
#pragma unroll
        for (int i = 0; i < 2; i++) {
            int id  = tid + i * 256;
            int row = id >> 2;
            int kc  = (id & 3) * 4;
            int grow = bm + row;
            float4 v = make_float4(0.f, 0.f, 0.f, 0.f);
            if (grow < M) v = *(const float4*)(A + (size_t)grow * 128 + k0 + kc);
            As[row][kc + 0] = f2tf32(v.x); As[row][kc + 1] = f2tf32(v.y);
            As[row][kc + 2] = f2tf32(v.z); As[row][kc + 3] = f2tf32(v.w);
        }
#pragma unroll
        for (int i = 0; i < 2; i++) {
            int id  = tid + i * 256;
            int row = id >> 5;
            int col = (id & 31) * 4;
            float4 v = *(const float4*)(W + (size_t)(k0 + row) * 128 + col);
            uint32_t h;
            h = f2tf32(v.x); Bs[row][col + 0] = h; Bl[row][col + 0] = f2tf32(v.x - __uint_as_float(h));
            h = f2tf32(v.y); Bs[row][col + 1] = h; Bl[row][col + 1] = f2tf32(v.y - __uint_as_float(h));
            h = f2tf32(v.z); Bs[row][col + 2] = h; Bl[row][col + 2] = f2tf32(v.z - __uint_as_float(h));
            h = f2tf32(v.w); Bs[row][col + 3] = h; Bl[row][col + 3] = f2tf32(v.w - __uint_as_float(h));
        }
        __syncthreads();

#pragma unroll
        for (int ks = 0; ks < 16; ks += 8) {
            uint32_t af[4][4];
            const int kc = ks + (lane & 3);
#pragma unroll
            for (int mf = 0; mf < 4; mf++) {
                int r = wm * 64 + mf * 16 + (lane >> 2);
                af[mf][0] = As[r][kc];
                af[mf][1] = As[r + 8][kc];
                af[mf][2] = As[r][kc + 4];
                af[mf][3] = As[r + 8][kc + 4];
            }
            uint32_t bh[4][2], bl[4][2];
#pragma unroll
            for (int nf = 0; nf < 4; nf++) {
                int n = wn * 32 + nf * 8 + (lane >> 2);
                bh[nf][0] = Bs[kc][n];     bl[nf][0] = Bl[kc][n];
                bh[nf][1] = Bs[kc + 4][n]; bl[nf][1] = Bl[kc + 4][n];
            }
#pragma unroll
            for (int mf = 0; mf < 4; mf++)
#pragma unroll
                for (int nf = 0; nf < 4; nf++) {
                    mma_tf32(acc[mf][nf], af[mf], bl[nf]);
                    mma_tf32(acc[mf][nf], af[mf], bh[nf]);
                }
        }
        __syncthreads();
    }

    const int lr = lane >> 2;
    const int lc = (lane & 3) * 2;
    float sk = 1.f / (1.f + __expf(-skipv[0]));
    float2 bv[4];
#pragma unroll
    for (int nf = 0; nf < 4; nf++) {
        int c0 = wn * 32 + nf * 8 + lc;
        bv[nf] = *(const float2*)(bias + c0);
    }

    float cs[4][2] = {{0.f,0.f},{0.f,0.f},{0.f,0.f},{0.f,0.f}};
    float cq[4][2] = {{0.f,0.f},{0.f,0.f},{0.f,0.f},{0.f,0.f}};

#pragma unroll
    for (int mf = 0; mf < 4; mf++) {
        int r0 = bm + wm * 64 + mf * 16 + lr;
        int r1 = r0 + 8;
#pragma unroll
        for (int nf = 0; nf < 4; nf++) {
            int c0 = wn * 32 + nf * 8 + lc;
            float4 a = acc[mf][nf];
            if (r0 < M) {
                float2 x0 = *(const float2*)(xold + (size_t)r0 * 128 + c0);
                float2 o0;
                o0.x = sk * (a.x + bv[nf].x) + (1.f - sk) * x0.x;
                o0.y = sk * (a.y + bv[nf].y) + (1.f - sk) * x0.y;
                cs[nf][0] += o0.x; cs[nf][1] += o0.y;
                cq[nf][0] += o0.x * o0.x; cq[nf][1] += o0.y * o0.y;
                *(float2*)(C + (size_t)r0 * 128 + c0) = o0;
            }
            if (r1 < M) {
                float2 x1 = *(const float2*)(xold + (size_t)r1 * 128 + c0);
                float2 o1;
                o1.x = sk * (a.z + bv[nf].x) + (1.f - sk) * x1.x;
                o1.y = sk * (a.w + bv[nf].y) + (1.f - sk) * x1.y;
                cs[nf][0] += o1.x; cs[nf][1] += o1.y;
                cq[nf][0] += o1.x * o1.x; cq[nf][1] += o1.y * o1.y;
                *(float2*)(C + (size_t)r1 * 128 + c0) = o1;
            }
        }
    }

    // BN stats reduction: per-channel sums into smem then one global atomic each.
    bnS[tid] = 0.f;
    __syncthreads();
#pragma unroll
    for (int nf = 0; nf < 4; nf++) {
        int c0 = wn * 32 + nf * 8 + lc;
        atomicAdd(&bnS[c0],       cs[nf][0]);
        atomicAdd(&bnS[c0 + 1],   cs[nf][1]);
        atomicAdd(&bnS[128 + c0],     cq[nf][0]);
        atomicAdd(&bnS[128 + c0 + 1], cq[nf][1]);
    }
    __syncthreads();
    atomicAdd(&stats[tid], bnS[tid]);
}

// ---------------- composite KV weights ----------------
__global__ void wcomp(const float* __restrict__ kqv_W, const float* __restrict__ a_k,
                      const float* __restrict__ a_v, float* __restrict__ WC)
{
    int gid = blockIdx.x * blockDim.x + threadIdx.x;
    if (gid >= 6 * 128 * 256) return;
    int lr = gid >> 15;
    int r  = (gid >> 8) & 127;
    int c  = gid & 255;
    int l = lr / 3, rel = lr % 3;
    int t = (rel == 0) ? 0 : 1;
    const float* Wb = kqv_W + (size_t)(l * 2 + t) * 128 * 384 + (size_t)r * 384 + ((c < 128) ? 0 : 256);
    int cc = c & 127;
    int h = cc >> 4, e = cc & 15;
    const float* Am = ((c < 128) ? a_k : a_v) + (size_t)(l * 3 + rel) * 2048 + h * 256 + e;
    float s = 0.f;
#pragma unroll
    for (int dd = 0; dd < 16; dd++) s += Wb[h * 16 + dd] * Am[dd * 16];
    WC[gid] = s;
}

__global__ void bcomp(const float* __restrict__ kqv_b, const float* __restrict__ a_k,
                      const float* __restrict__ a_v, float* __restrict__ WCB)
{
    int gid = blockIdx.x * blockDim.x + threadIdx.x;
    if (gid >= 6 * 256) return;
    int lr = gid >> 8;
    int c  = gid & 255;
    int l = lr / 3, rel = lr % 3;
    int t = (rel == 0) ? 0 : 1;
    const float* bb = kqv_b + (size_t)(l * 2 + t) * 384 + ((c < 128) ? 0 : 256);
    int cc = c & 127;
    int h = cc >> 4, e = cc & 15;
    const float* Am = ((c < 128) ? a_k : a_v) + (size_t)(l * 3 + rel) * 2048 + h * 256 + e;
    float s = 0.f;
#pragma unroll
    for (int dd = 0; dd < 16; dd++) s += bb[h * 16 + dd] * Am[dd * 16];
    WCB[gid] = s;
}

// ---------------- CSR build ----------------
__global__ void hist_kernel(const int* __restrict__ dst, int* __restrict__ deg, int E)
{
    int i = blockIdx.x * blockDim.x + threadIdx.x;
    if (i < E) atomicAdd(&deg[dst[i]], 1);
}

__global__ void scan_partial(const int* __restrict__ deg, int* __restrict__ row,
                             int* __restrict__ bsums, int n)
{
    __shared__ int warpsum[8];
    int t = threadIdx.x;
    int lane = t & 31, wid = t >> 5;
    int base = blockIdx.x * 1024 + t * 4;
    int v0 = (base + 0 < n) ? deg[base + 0] : 0;
    int v1 = (base + 1 < n) ? deg[base + 1] : 0;
    int v2 = (base + 2 < n) ? deg[base + 2] : 0;
    int v3 = (base + 3 < n) ? deg[base + 3] : 0;
    int e0 = 0, e1 = v0, e2 = e1 + v1, e3 = e2 + v2;
    int tot = e3 + v3;
    int inc = tot;
#pragma unroll
    for (int off = 1; off < 32; off <<= 1) {
        int y = __shfl_up_sync(0xffffffffu, inc, off);
        if (lane >= off) inc += y;
    }
    if (lane == 31) warpsum[wid] = inc;
    __syncthreads();
    if (wid == 0) {
        int w = (lane < 8) ? warpsum[lane] : 0;
#pragma unroll
        for (int off = 1; off < 8; off <<= 1) {
            int y = __shfl_up_sync(0xffffffffu, w, off);
            if (lane >= off) w += y;
        }
        if (lane < 8) warpsum[lane] = w;
    }
    __syncthreads();
    int warpExcl = (wid == 0) ? 0 : warpsum[wid - 1];
    int thrExcl = warpExcl + inc - tot;
    if (base + 0 < n) row[base + 0] = thrExcl + e0;
    if (base + 1 < n) row[base + 1] = thrExcl + e1;
    if (base + 2 < n) row[base + 2] = thrExcl + e2;
    if (base + 3 < n) row[base + 3] = thrExcl + e3;
    if (t == 0) bsums[blockIdx.x] = warpsum[7];
}

__global__ void scan_small(int* __restrict__ bsums, int nb)
{
    __shared__ int warpsum[8];
    int t = threadIdx.x;
    int lane = t & 31, wid = t >> 5;
    int v = (t < nb) ? bsums[t] : 0;
    int inc = v;
#pragma unroll
    for (int off = 1; off < 32; off <<= 1) {
        int y = __shfl_up_sync(0xffffffffu, inc, off);
        if (lane >= off) inc += y;
    }
    if (lane == 31) warpsum[wid] = inc;
    __syncthreads();
    if (wid == 0) {
        int w = (lane < 8) ? warpsum[lane] : 0;
#pragma unroll
        for (int off = 1; off < 8; off <<= 1) {
            int y = __shfl_up_sync(0xffffffffu, w, off);
            if (lane >= off) w += y;
        }
        if (lane < 8) warpsum[lane] = w;
    }
    __syncthreads();
    int warpExcl = (wid == 0) ? 0 : warpsum[wid - 1];
    int excl = warpExcl + inc - v;
    if (t < nb) bsums[t] = excl;
    if (t == 255) bsums[nb] = warpExcl + inc;
}

__global__ void add_off(int* __restrict__ row, int* __restrict__ cur,
                        const int* __restrict__ bsums, int n, int nb)
{
    int i = blockIdx.x * blockDim.x + threadIdx.x;
    if (i < n) {
        int r = row[i] + bsums[i >> 10];
        row[i] = r;
        cur[i] = r;
    }
    if (i == 0) row[n] = bsums[nb];
}

__global__ void scatter_kernel(const int* __restrict__ src, const int* __restrict__ dst,
                               int* __restrict__ cursor, int* __restrict__ out,
                               int E, int srcOffset)
{
    int i = blockIdx.x * blockDim.x + threadIdx.x;
    if (i >= E) return;
    int p = atomicAdd(&cursor[dst[i]], 1);
    out[p] = src[i] + srcOffset;
}

// ---------------- fused attention (both node types in one launch) ----------------
__global__ void attn_agg2(const float* __restrict__ QP, const __half* __restrict__ KVP,
                          const int* __restrict__ rowP, const int* __restrict__ srcP,
                          const float* __restrict__ prelP_A, const float* __restrict__ prelP_B,
                          const float* __restrict__ QA, const __half* __restrict__ KVA,
                          const int* __restrict__ rowA, const int* __restrict__ srcA,
                          const float* __restrict__ prelA_r,
                          float* __restrict__ aggP, float* __restrict__ aggA)
{
    int gwarp = (blockIdx.x * blockDim.x + threadIdx.x) >> 5;
    int lane = threadIdx.x & 31;
    if (gwarp >= NP + NA) return;

    const float* Q; const __half* KV; const int* rowptr; const int* srccol;
    const float* prA; const float* prB; int relB; float* agg; int node;
    if (gwarp < NP) {
        node = gwarp; Q = QP; KV = KVP; rowptr = rowP; srccol = srcP;
        prA = prelP_A; prB = prelP_B; relB = NA; agg = aggP;
    } else {
        node = gwarp - NP; Q = QA; KV = KVA; rowptr = rowA; srccol = srcA;
        prA = prelA_r; prB = prelA_r; relB = NP + 1; agg = aggA;
    }

    int h = lane >> 2;
    int c = h * 16 + (lane & 3) * 4;
    float4 q4 = *(const float4*)(Q + (size_t)node * 128 + c);
    float pA = prA[h] * 0.25f;
    float pB = prB[h] * 0.25f;
    int js = rowptr[node], je = rowptr[node + 1];
    float m = -INFINITY, s = 0.f;
    float4 acc = make_float4(0.f, 0.f, 0.f, 0.f);

    int j = js;
    for (; j + 1 < je; j += 2) {
        int sr1 = srccol[j];
        int sr2 = srccol[j + 1];
        const __half2* kp1 = (const __half2*)(KV + (size_t)sr1 * 256 + c);
        const __half2* kp2 = (const __half2*)(KV + (size_t)sr2 * 256 + c);
        float2 k10 = __half22float2(kp1[0]), k11 = __half22float2(kp1[1]);
        float2 k20 = __half22float2(kp2[0]), k21 = __half22float2(kp2[1]);
        float p1 = q4.x * k10.x + q4.y * k10.y + q4.z * k11.x + q4.w * k11.y;
        float p2 = q4.x * k20.x + q4.y * k20.y + q4.z * k21.x + q4.w * k21.y;
        p1 += __shfl_xor_sync(0xffffffffu, p1, 1);
        p2 += __shfl_xor_sync(0xffffffffu, p2, 1);
        p1 += __shfl_xor_sync(0xffffffffu, p1, 2);
        p2 += __shfl_xor_sync(0xffffffffu, p2, 2);
        float a1 = p1 * ((sr1 >= relB) ? pB : pA);
        float a2 = p2 * ((sr2 >= relB) ? pB : pA);
        const __half2* vp1 = (const __half2*)(KV + (size_t)sr1 * 256 + 128 + c);
        const __half2* vp2 = (const __half2*)(KV + (size_t)sr2 * 256 + 128 + c);
        float2 v10 = __half22float2(vp1[0]), v11 = __half22float2(vp1[1]);
        float2 v20 = __half22float2(vp2[0]), v21 = __half22float2(vp2[1]);
        float newm = fmaxf(m, fmaxf(a1, a2));
        float scl = __expf(m - newm);
        float w1 = __expf(a1 - newm);
        float w2 = __expf(a2 - newm);
        s = s * scl + w1 + w2;
        acc.x = acc.x * scl + w1 * v10.x + w2 * v20.x;
        acc.y = acc.y * scl + w1 * v10.y + w2 * v20.y;
        acc.z = acc.z * scl + w1 * v11.x + w2 * v21.x;
        acc.w = acc.w * scl + w1 * v11.y + w2 * v21.y;
        m = newm;
    }
    for (; j < je; j++) {
        int sr = srccol[j];
        const __half2* kp = (const __half2*)(KV + (size_t)sr * 256 + c);
        float2 k0 = __half22float2(kp[0]), k1 = __half22float2(kp[1]);
        float part = q4.x * k0.x + q4.y * k0.y + q4.z * k1.x + q4.w * k1.y;
        part += __shfl_xor_sync(0xffffffffu, part, 1);
        part += __shfl_xor_sync(0xffffffffu, part, 2);
        float a = part * ((sr >= relB) ? pB : pA);
        float newm = fmaxf(m, a);
        float scl = __expf(m - newm);
        float w = __expf(a - newm);
        s = s * scl + w;
        const __half2* vp = (const __half2*)(KV + (size_t)sr * 256 + 128 + c);
        float2 v0 = __half22float2(vp[0]), v1 = __half22float2(vp[1]);
        acc.x = acc.x * scl + w * v0.x;
        acc.y = acc.y * scl + w * v0.y;
        acc.z = acc.z * scl + w * v1.x;
        acc.w = acc.w * scl + w * v1.y;
        m = newm;
    }

    float inv = 1.f / (s + 1e-16f);
    float4 r;
    float v;
    v = acc.x * inv; r.x = 0.5f * v * (1.f + erff(v * 0.70710678118654752f));
    v = acc.y * inv; r.y = 0.5f * v * (1.f + erff(v * 0.70710678118654752f));
    v = acc.z * inv; r.z = 0.5f * v * (1.f + erff(v * 0.70710678118654752f));
    v = acc.w * inv; r.w = 0.5f * v * (1.f + erff(v * 0.70710678118654752f));
    *(float4*)(agg + (size_t)node * 128 + c) = r;
}

// ---------------- BatchNorm apply (both node types in one launch) ----------------
__global__ void bn_apply2(const float* __restrict__ hA, const float* __restrict__ hP,
                          const float* __restrict__ stats,
                          const float* __restrict__ gamma, const float* __restrict__ beta,
                          float* __restrict__ outA, float* __restrict__ outP)
{
    int i = blockIdx.x * blockDim.x + threadIdx.x;
    const int totA = NA * 128;
    const int totP = NP * 128;
    if (i < totA) {
        int c = i & 127;
        float invN = 1.f / (float)NA;
        float mu = stats[c] * invN;
        float var = stats[128 + c] * invN - mu * mu;
        outA[i] = (hA[i] - mu) * rsqrtf(var + BN_EPS) * gamma[c] + beta[c];
    } else {
        int k = i - totA;
        if (k >= totP) return;
        int c = k & 127;
        float invN = 1.f / (float)NP;
        float mu = stats[256 + c] * invN;
        float var = stats[256 + 128 + c] * invN - mu * mu;
        outP[k] = (hP[k] - mu) * rsqrtf(var + BN_EPS) * gamma[c] + beta[c];
    }
}

// ---------------------------------------------------------------
static inline int cdiv(long long a, long long b) { return (int)((a + b - 1) / b); }

extern "C" void kernel_launch(void* const* d_in, const int* in_sizes, int n_in,
                              void* d_out, int out_size)
{
    const float* x_author = (const float*)d_in[0];
    const float* x_paper  = (const float*)d_in[1];
    const int* writes_src = (const int*)d_in[2];
    const int* writes_dst = (const int*)d_in[3];
    const int* rev_src    = (const int*)d_in[4];
    const int* rev_dst    = (const int*)d_in[5];
    const int* cites_src  = (const int*)d_in[6];
    const int* cites_dst  = (const int*)d_in[7];
    const float* linA_W   = (const float*)d_in[8];
    const float* linA_b   = (const float*)d_in[9];
    const float* linP_W   = (const float*)d_in[10];
    const float* linP_b   = (const float*)d_in[11];
    const float* kqv_W    = (const float*)d_in[12];
    const float* kqv_b    = (const float*)d_in[13];
    const float* a_k      = (const float*)d_in[14];
    const float* a_v      = (const float*)d_in[15];
    const float* p_rel    = (const float*)d_in[16];
    const float* out_W    = (const float*)d_in[17];
    const float* out_b    = (const float*)d_in[18];
    const float* skipP    = (const float*)d_in[19];
    const float* bn_gamma = (const float*)d_in[20];
    const float* bn_beta  = (const float*)d_in[21];

    float* base = nullptr;
    cudaGetSymbolAddress((void**)&base, g_scratch);

    float* XA   = base + OFF_XA;
    float* XP   = base + OFF_XP;
    float* QA   = base + OFF_QA;
    float* QP   = base + OFF_QP;
    __half* KVP = (__half*)(base + OFF_KVP);
    __half* KVA = (__half*)(base + OFF_KVA);
    float* AGGA = base + OFF_AGGA;
    float* AGGP = base + OFF_AGGP;
    float* TMPA = base + OFF_TMPA;
    float* TMPP = base + OFF_TMPP;
    float* WC   = base + OFF_WC;
    float* WCB  = base + OFF_WCB;
    float* STA  = base + OFF_STATS;        // [0:256) author, [256:512) paper
    int* ibase  = (int*)(base + OFF_INT);
    int* ROWP   = ibase + IOFF_ROWP;
    int* ROWA   = ibase + IOFF_ROWA;
    int* CURP   = ibase + IOFF_CURP;
    int* CURA   = ibase + IOFF_CURA;
    int* SRCP   = ibase + IOFF_SRCP;
    int* SRCA   = ibase + IOFF_SRCA;
    int* BS     = ibase + IOFF_BS;

    // -------- CSR build + composite weights (x-independent) --------
    const int nbP = cdiv(NP, 1024), nbA = cdiv(NA, 1024);
    cudaMemsetAsync(CURP, 0, (size_t)NP * 4, 0);
    cudaMemsetAsync(CURA, 0, (size_t)NA * 4, 0);
    hist_kernel<<<cdiv(EW, 256), 256>>>(writes_dst, CURP, EW);
    hist_kernel<<<cdiv(EC, 256), 256>>>(cites_dst, CURP, EC);
    hist_kernel<<<cdiv(ER, 256), 256>>>(rev_dst, CURA, ER);
    scan_partial<<<nbP, 256>>>(CURP, ROWP, BS, NP);
    scan_small<<<1, 256>>>(BS, nbP);
    add_off<<<cdiv(NP, 256), 256>>>(ROWP, CURP, BS, NP, nbP);
    scan_partial<<<nbA, 256>>>(CURA, ROWA, BS, NA);
    scan_small<<<1, 256>>>(BS, nbA);
    add_off<<<cdiv(NA, 256), 256>>>(ROWA, CURA, BS, NA, nbA);
    scatter_kernel<<<cdiv(EW, 256), 256>>>(writes_src, writes_dst, CURP, SRCP, EW, 0);
    scatter_kernel<<<cdiv(EC, 256), 256>>>(cites_src, cites_dst, CURP, SRCP, EC, NA);
    scatter_kernel<<<cdiv(ER, 256), 256>>>(rev_src, rev_dst, CURA, SRCA, ER, 0);
    wcomp<<<768, 256>>>(kqv_W, a_k, a_v, WC);
    bcomp<<<6, 256>>>(kqv_b, a_k, a_v, WCB);

    // -------- input projections + relu --------
    gemm_tf32<<<dim3(1, cdiv(NA, 128)), 256>>>(x_author, 128, linA_W, 128, linA_b,
                                               XA, nullptr, 128, NA, 128, 1, nullptr, nullptr);
    gemm_tf32<<<dim3(1, cdiv(NP, 128)), 256>>>(x_paper, 128, linP_W, 128, linP_b,
                                               XP, nullptr, 128, NP, 128, 1, nullptr, nullptr);

    for (int l = 0; l < 2; l++) {
        // Q projections (Q slice of kqv weights: cols [128,256))
        gemm_tf32<<<dim3(1, cdiv(NA, 128)), 256>>>(XA, 128, kqv_W + (size_t)(l * 2 + 0) * 128 * 384 + 128, 384,
                                                   kqv_b + (size_t)(l * 2 + 0) * 384 + 128,
                                                   QA, nullptr, 128, NA, 128, 0, nullptr, nullptr);
        gemm_tf32<<<dim3(1, cdiv(NP, 128)), 256>>>(XP, 128, kqv_W + (size_t)(l * 2 + 1) * 128 * 384 + 128, 384,
                                                   kqv_b + (size_t)(l * 2 + 1) * 384 + 128,
                                                   QP, nullptr, 128, NP, 128, 0, nullptr, nullptr);

        // combined K|V tables via composite weights, fp16 output
        gemm_tf32<<<dim3(2, cdiv(NA, 128)), 256>>>(XA, 128, WC + (size_t)(l * 3 + 0) * 128 * 256, 256,
                                                   WCB + (size_t)(l * 3 + 0) * 256,
                                                   nullptr, KVP, 256, NA, 128, 0, nullptr, nullptr);
        gemm_tf32<<<dim3(2, cdiv(NP, 128)), 256>>>(XP, 128, WC + (size_t)(l * 3 + 2) * 128 * 256, 256,
                                                   WCB + (size_t)(l * 3 + 2) * 256,
                                                   nullptr, KVP + (size_t)NA * 256, 256, NP, 128, 0, nullptr, nullptr);
        gemm_tf32<<<dim3(2, cdiv(NP, 128)), 256>>>(XP, 128, WC + (size_t)(l * 3 + 1) * 128 * 256, 256,
                                                   WCB + (size_t)(l * 3 + 1) * 256,
                                                   nullptr, KVA, 256, NP, 128, 0, nullptr, nullptr);

        // fused attention + softmax + aggregation + gelu (single launch, both types)
        attn_agg2<<<cdiv((long long)(NP + NA) * 32, 256), 256>>>(
            QP, KVP, ROWP, SRCP,
            p_rel + (size_t)(l * 3 + 0) * NH, p_rel + (size_t)(l * 3 + 2) * NH,
            QA, KVA, ROWA, SRCA,
            p_rel + (size_t)(l * 3 + 1) * NH,
            AGGP, AGGA);

        // output projection + fused skip-mix + fused BN stats (dedicated kernel)
        cudaMemsetAsync(STA, 0, 512 * 4, 0);
        gemm_out<<<dim3(1, cdiv(NA, 128)), 256>>>(AGGA, out_W + (size_t)(l * 2 + 0) * 128 * 128,
                                                  out_b + (size_t)(l * 2 + 0) * 128,
                                                  TMPA, NA, XA, skipP + (l * 2 + 0), STA);
        gemm_out<<<dim3(1, cdiv(NP, 128)), 256>>>(AGGP, out_W + (size_t)(l * 2 + 1) * 128 * 128,
                                                  out_b + (size_t)(l * 2 + 1) * 128,
                                                  TMPP, NP, XP, skipP + (l * 2 + 1), STA + 256);

        // batch norm apply (single launch, both types)
        float* outA = (l == 1) ? (float*)d_out : XA;
        float* outP = (l == 1) ? (float*)d_out + (size_t)NA * 128 : XP;
        bn_apply2<<<cdiv((long long)(NA + NP) * 128, 256), 256>>>(TMPA, TMPP, STA,
                                                                  bn_gamma + (size_t)l * 128,
                                                                  bn_beta + (size_t)l * 128,
                                                                  outA, outP);
    }
}

// round 13
// speedup vs baseline: 1.0831x; 1.0831x over previous
#include <cuda_runtime.h>
#include <cuda_fp16.h>
#include <math.h>
#include <stdint.h>

// ---------------- problem sizes ----------------
#define NA 50000
#define NP 100000
#define HC 128
#define NH 8
#define EW 400000
#define ER 400000
#define EC 800000
#define EP (EW + EC)
#define BN_EPS 1e-5f

// ---------------- scratch layout (float units) ----------------
#define OFF_XA    0ull
#define OFF_XP    (OFF_XA   + (size_t)NA*128)
#define OFF_A384  (OFF_XP   + (size_t)NP*128)        // half[NA*384] : Q | K_rel0 | V_rel0
#define OFF_P640  (OFF_A384 + (size_t)NA*192)        // half[NP*640] : Q | K_rel2 | V_rel2 | K_rel1 | V_rel1
#define OFF_AGGA  (OFF_P640 + (size_t)NP*320)
#define OFF_AGGP  (OFF_AGGA + (size_t)NA*128)
#define OFF_TMPA  (OFF_AGGP + (size_t)NP*128)
#define OFF_TMPP  (OFF_TMPA + (size_t)NA*128)
#define OFF_WA    (OFF_TMPP + (size_t)NP*128)        // 2 * 128 * 384
#define OFF_WP    (OFF_WA   + 2ull*128*384)          // 2 * 128 * 640
#define OFF_WAB   (OFF_WP   + 2ull*128*640)          // 2 * 384
#define OFF_WPB   (OFF_WAB  + 2ull*384)              // 2 * 640
#define OFF_STATS (OFF_WPB  + 2ull*640)
// integer region
#define OFF_INT   (OFF_STATS + 512ull)
#define IOFF_ROWP 0ull
#define IOFF_ROWA (IOFF_ROWP + NP + 1)
#define IOFF_CURP (IOFF_ROWA + NA + 1)
#define IOFF_CURA (IOFF_CURP + NP)
#define IOFF_SRCP (IOFF_CURA + NA)
#define IOFF_SRCA (IOFF_SRCP + EP)
#define IOFF_BS   (IOFF_SRCA + ER)
#define INT_TOTAL (IOFF_BS + 256)
#define TOTAL_FLOATS (OFF_INT + INT_TOTAL + 64ull)

__device__ float g_scratch[TOTAL_FLOATS];

// ---------------- tf32 helpers ----------------
__device__ __forceinline__ uint32_t f2tf32(float x)
{
    uint32_t r;
    asm("cvt.rna.tf32.f32 %0, %1;" : "=r"(r) : "f"(x));
    return r;
}

__device__ __forceinline__ void mma_tf32(float4& c, const uint32_t* a, const uint32_t* b)
{
    asm volatile(
        "mma.sync.aligned.m16n8k8.row.col.f32.tf32.tf32.f32 "
        "{%0,%1,%2,%3}, {%4,%5,%6,%7}, {%8,%9}, {%0,%1,%2,%3};"
        : "+f"(c.x), "+f"(c.y), "+f"(c.z), "+f"(c.w)
        : "r"(a[0]), "r"(a[1]), "r"(a[2]), "r"(a[3]), "r"(b[0]), "r"(b[1]));
}

__device__ __forceinline__ float4 ld4h(const __half* p)
{
    __half2 a = *(const __half2*)p;
    __half2 b = *(const __half2*)(p + 2);
    float2 fa = __half22float2(a), fb = __half22float2(b);
    return make_float4(fa.x, fa.y, fb.x, fb.y);
}

// ---------------- tf32x2 tensor-core GEMM (EXACT R8/R11 form) ----------------
// C[M, gridN] = A[M,K] @ W[K,*] + bias. BM=128, BN=128, BK=16, 8 warps 2x4.
// Ch != nullptr -> half output (C ignored). act: 0=none, 1=relu, 2=skip-mix
__global__ void __launch_bounds__(256)
gemm_tf32(const float* __restrict__ A, int lda, const float* __restrict__ W, int ldw,
          const float* __restrict__ bias, float* __restrict__ C, __half* __restrict__ Ch,
          int ldc, int M, int K, int act,
          const float* __restrict__ xold, const float* __restrict__ skipv)
{
    __shared__ uint32_t As[128][20];
    __shared__ uint32_t Bs[16][136], Bl[16][136];

    const int bm = blockIdx.y * 128;
    const int bn = blockIdx.x * 128;
    const int tid = threadIdx.x;
    const int lane = tid & 31;
    const int warp = tid >> 5;
    const int wm = warp >> 2;
    const int wn = warp & 3;

    float4 acc[4][4];
#pragma unroll
    for (int i = 0; i < 4; i++)
#pragma unroll
        for (int j = 0; j < 4; j++) acc[i][j] = make_float4(0.f, 0.f, 0.f, 0.f);

    for (int k0 = 0; k0 < K; k0 += 16) {
#pragma unroll
        for (int i = 0; i < 2; i++) {
            int id  = tid + i * 256;
            int row = id >> 2;
            int kc  = (id & 3) * 4;
            int grow = bm + row;
            float4 v = make_float4(0.f, 0.f, 0.f, 0.f);
            if (grow < M) v = *(const float4*)(A + (size_t)grow * lda + k0 + kc);
            As[row][kc + 0] = f2tf32(v.x); As[row][kc + 1] = f2tf32(v.y);
            As[row][kc + 2] = f2tf32(v.z); As[row][kc + 3] = f2tf32(v.w);
        }
#pragma unroll
        for (int i = 0; i < 2; i++) {
            int id  = tid + i * 256;
            int row = id >> 5;
            int col = (id & 31) * 4;
            float4 v = *(const float4*)(W + (size_t)(k0 + row) * ldw + bn + col);
            uint32_t h;
            h = f2tf32(v.x); Bs[row][col + 0] = h; Bl[row][col + 0] = f2tf32(v.x - __uint_as_float(h));
            h = f2tf32(v.y); Bs[row][col + 1] = h; Bl[row][col + 1] = f2tf32(v.y - __uint_as_float(h));
            h = f2tf32(v.z); Bs[row][col + 2] = h; Bl[row][col + 2] = f2tf32(v.z - __uint_as_float(h));
            h = f2tf32(v.w); Bs[row][col + 3] = h; Bl[row][col + 3] = f2tf32(v.w - __uint_as_float(h));
        }
        __syncthreads();

#pragma unroll
        for (int ks = 0; ks < 16; ks += 8) {
            uint32_t af[4][4];
            const int kc = ks + (lane & 3);
#pragma unroll
            for (int mf = 0; mf < 4; mf++) {
                int r = wm * 64 + mf * 16 + (lane >> 2);
                af[mf][0] = As[r][kc];
                af[mf][1] = As[r + 8][kc];
                af[mf][2] = As[r][kc + 4];
                af[mf][3] = As[r + 8][kc + 4];
            }
            uint32_t bh[4][2], bl[4][2];
#pragma unroll
            for (int nf = 0; nf < 4; nf++) {
                int n = wn * 32 + nf * 8 + (lane >> 2);
                bh[nf][0] = Bs[kc][n];     bl[nf][0] = Bl[kc][n];
                bh[nf][1] = Bs[kc + 4][n]; bl[nf][1] = Bl[kc + 4][n];
            }
#pragma unroll
            for (int mf = 0; mf < 4; mf++)
#pragma unroll
                for (int nf = 0; nf < 4; nf++) {
                    mma_tf32(acc[mf][nf], af[mf], bl[nf]);
                    mma_tf32(acc[mf][nf], af[mf], bh[nf]);
                }
        }
        __syncthreads();
    }

    const int lr = lane >> 2;
    const int lc = (lane & 3) * 2;
    float sk = 0.f;
    if (act == 2) sk = 1.f / (1.f + __expf(-skipv[0]));
    float2 bv[4];
#pragma unroll
    for (int nf = 0; nf < 4; nf++) {
        int c0 = bn + wn * 32 + nf * 8 + lc;
        bv[nf] = *(const float2*)(bias + c0);
    }
#pragma unroll
    for (int mf = 0; mf < 4; mf++) {
        int r0 = bm + wm * 64 + mf * 16 + lr;
        int r1 = r0 + 8;
#pragma unroll
        for (int nf = 0; nf < 4; nf++) {
            int c0 = bn + wn * 32 + nf * 8 + lc;
            float4 a = acc[mf][nf];
            float2 o0 = make_float2(a.x + bv[nf].x, a.y + bv[nf].y);
            float2 o1 = make_float2(a.z + bv[nf].x, a.w + bv[nf].y);
            if (act == 1) {
                o0.x = fmaxf(o0.x, 0.f); o0.y = fmaxf(o0.y, 0.f);
                o1.x = fmaxf(o1.x, 0.f); o1.y = fmaxf(o1.y, 0.f);
            } else if (act == 2) {
                if (r0 < M) {
                    float2 x0 = *(const float2*)(xold + (size_t)r0 * ldc + c0);
                    o0.x = sk * o0.x + (1.f - sk) * x0.x;
                    o0.y = sk * o0.y + (1.f - sk) * x0.y;
                }
                if (r1 < M) {
                    float2 x1 = *(const float2*)(xold + (size_t)r1 * ldc + c0);
                    o1.x = sk * o1.x + (1.f - sk) * x1.x;
                    o1.y = sk * o1.y + (1.f - sk) * x1.y;
                }
            }
            if (Ch) {
                if (r0 < M) *(__half2*)(Ch + (size_t)r0 * ldc + c0) = __floats2half2_rn(o0.x, o0.y);
                if (r1 < M) *(__half2*)(Ch + (size_t)r1 * ldc + c0) = __floats2half2_rn(o1.x, o1.y);
            } else {
                if (r0 < M) *(float2*)(C + (size_t)r0 * ldc + c0) = o0;
                if (r1 < M) *(float2*)(C + (size_t)r1 * ldc + c0) = o1;
            }
        }
    }
}

// ---------------- composite weights: author [128x384], paper [128x640] --------
// Author cols: [0,128) Q slice; [128,256) K_rel0; [256,384) V_rel0.
// Paper  cols: [0,128) Q slice; [128,256) K_rel2; [256,384) V_rel2;
//              [384,512) K_rel1; [512,640) V_rel1.
__global__ void wcompA(const float* __restrict__ kqv_W, const float* __restrict__ a_k,
                       const float* __restrict__ a_v, float* __restrict__ WA)
{
    int gid = blockIdx.x * blockDim.x + threadIdx.x;
    if (gid >= 2 * 128 * 384) return;
    int l = gid / (128 * 384);
    int rem = gid % (128 * 384);
    int r = rem / 384, c = rem % 384;
    const float* Wrow = kqv_W + (size_t)(l * 2 + 0) * 128 * 384 + (size_t)r * 384;
    float s;
    if (c < 128) {
        s = Wrow[128 + c];
    } else {
        int cc = c - 128;
        int c2 = cc & 127, h = c2 >> 4, e = c2 & 15;
        const float* Wb = Wrow + ((cc < 128) ? 0 : 256);
        const float* Am = ((cc < 128) ? a_k : a_v) + (size_t)(l * 3 + 0) * 2048 + h * 256 + e;
        s = 0.f;
#pragma unroll
        for (int dd = 0; dd < 16; dd++) s += Wb[h * 16 + dd] * Am[dd * 16];
    }
    WA[gid] = s;
}

__global__ void wcompP(const float* __restrict__ kqv_W, const float* __restrict__ a_k,
                       const float* __restrict__ a_v, float* __restrict__ WP)
{
    int gid = blockIdx.x * blockDim.x + threadIdx.x;
    if (gid >= 2 * 128 * 640) return;
    int l = gid / (128 * 640);
    int rem = gid % (128 * 640);
    int r = rem / 640, c = rem % 640;
    const float* Wrow = kqv_W + (size_t)(l * 2 + 1) * 128 * 384 + (size_t)r * 384;
    float s;
    if (c < 128) {
        s = Wrow[128 + c];
    } else {
        int rel = (c < 384) ? 2 : 1;
        int cc = (c < 384) ? (c - 128) : (c - 384);
        int c2 = cc & 127, h = c2 >> 4, e = c2 & 15;
        const float* Wb = Wrow + ((cc < 128) ? 0 : 256);
        const float* Am = ((cc < 128) ? a_k : a_v) + (size_t)(l * 3 + rel) * 2048 + h * 256 + e;
        s = 0.f;
#pragma unroll
        for (int dd = 0; dd < 16; dd++) s += Wb[h * 16 + dd] * Am[dd * 16];
    }
    WP[gid] = s;
}

__global__ void bcompA(const float* __restrict__ kqv_b, const float* __restrict__ a_k,
                       const float* __restrict__ a_v, float* __restrict__ WAB)
{
    int gid = blockIdx.x * blockDim.x + threadIdx.x;
    if (gid >= 2 * 384) return;
    int l = gid / 384, c = gid % 384;
    const float* brow = kqv_b + (size_t)(l * 2 + 0) * 384;
    float s;
    if (c < 128) {
        s = brow[128 + c];
    } else {
        int cc = c - 128;
        int c2 = cc & 127, h = c2 >> 4, e = c2 & 15;
        const float* bb = brow + ((cc < 128) ? 0 : 256);
        const float* Am = ((cc < 128) ? a_k : a_v) + (size_t)(l * 3 + 0) * 2048 + h * 256 + e;
        s = 0.f;
#pragma unroll
        for (int dd = 0; dd < 16; dd++) s += bb[h * 16 + dd] * Am[dd * 16];
    }
    WAB[gid] = s;
}

__global__ void bcompP(const float* __restrict__ kqv_b, const float* __restrict__ a_k,
                       const float* __restrict__ a_v, float* __restrict__ WPB)
{
    int gid = blockIdx.x * blockDim.x + threadIdx.x;
    if (gid >= 2 * 640) return;
    int l = gid / 640, c = gid % 640;
    const float* brow = kqv_b + (size_t)(l * 2 + 1) * 384;
    float s;
    if (c < 128) {
        s = brow[128 + c];
    } else {
        int rel = (c < 384) ? 2 : 1;
        int cc = (c < 384) ? (c - 128) : (c - 384);
        int c2 = cc & 127, h = c2 >> 4, e = c2 & 15;
        const float* bb = brow + ((cc < 128) ? 0 : 256);
        const float* Am = ((cc < 128) ? a_k : a_v) + (size_t)(l * 3 + rel) * 2048 + h * 256 + e;
        s = 0.f;
#pragma unroll
        for (int dd = 0; dd < 16; dd++) s += bb[h * 16 + dd] * Am[dd * 16];
    }
    WPB[gid] = s;
}

// ---------------- CSR build ----------------
__global__ void hist_kernel(const int* __restrict__ dst, int* __restrict__ deg, int E)
{
    int i = blockIdx.x * blockDim.x + threadIdx.x;
    if (i < E) atomicAdd(&deg[dst[i]], 1);
}

__global__ void scan_partial(const int* __restrict__ deg, int* __restrict__ row,
                             int* __restrict__ bsums, int n)
{
    __shared__ int warpsum[8];
    int t = threadIdx.x;
    int lane = t & 31, wid = t >> 5;
    int base = blockIdx.x * 1024 + t * 4;
    int v0 = (base + 0 < n) ? deg[base + 0] : 0;
    int v1 = (base + 1 < n) ? deg[base + 1] : 0;
    int v2 = (base + 2 < n) ? deg[base + 2] : 0;
    int v3 = (base + 3 < n) ? deg[base + 3] : 0;
    int e0 = 0, e1 = v0, e2 = e1 + v1, e3 = e2 + v2;
    int tot = e3 + v3;
    int inc = tot;
#pragma unroll
    for (int off = 1; off < 32; off <<= 1) {
        int y = __shfl_up_sync(0xffffffffu, inc, off);
        if (lane >= off) inc += y;
    }
    if (lane == 31) warpsum[wid] = inc;
    __syncthreads();
    if (wid == 0) {
        int w = (lane < 8) ? warpsum[lane] : 0;
#pragma unroll
        for (int off = 1; off < 8; off <<= 1) {
            int y = __shfl_up_sync(0xffffffffu, w, off);
            if (lane >= off) w += y;
        }
        if (lane < 8) warpsum[lane] = w;
    }
    __syncthreads();
    int warpExcl = (wid == 0) ? 0 : warpsum[wid - 1];
    int thrExcl = warpExcl + inc - tot;
    if (base + 0 < n) row[base + 0] = thrExcl + e0;
    if (base + 1 < n) row[base + 1] = thrExcl + e1;
    if (base + 2 < n) row[base + 2] = thrExcl + e2;
    if (base + 3 < n) row[base + 3] = thrExcl + e3;
    if (t == 0) bsums[blockIdx.x] = warpsum[7];
}

__global__ void scan_small(int* __restrict__ bsums, int nb)
{
    __shared__ int warpsum[8];
    int t = threadIdx.x;
    int lane = t & 31, wid = t >> 5;
    int v = (t < nb) ? bsums[t] : 0;
    int inc = v;
#pragma unroll
    for (int off = 1; off < 32; off <<= 1) {
        int y = __shfl_up_sync(0xffffffffu, inc, off);
        if (lane >= off) inc += y;
    }
    if (lane == 31) warpsum[wid] = inc;
    __syncthreads();
    if (wid == 0) {
        int w = (lane < 8) ? warpsum[lane] : 0;
#pragma unroll
        for (int off = 1; off < 8; off <<= 1) {
            int y = __shfl_up_sync(0xffffffffu, w, off);
            if (lane >= off) w += y;
        }
        if (lane < 8) warpsum[lane] = w;
    }
    __syncthreads();
    int warpExcl = (wid == 0) ? 0 : warpsum[wid - 1];
    int excl = warpExcl + inc - v;
    if (t < nb) bsums[t] = excl;
    if (t == 255) bsums[nb] = warpExcl + inc;
}

__global__ void add_off(int* __restrict__ row, int* __restrict__ cur,
                        const int* __restrict__ bsums, int n, int nb)
{
    int i = blockIdx.x * blockDim.x + threadIdx.x;
    if (i < n) {
        int r = row[i] + bsums[i >> 10];
        row[i] = r;
        cur[i] = r;
    }
    if (i == 0) row[n] = bsums[nb];
}

__global__ void scatter_kernel(const int* __restrict__ src, const int* __restrict__ dst,
                               int* __restrict__ cursor, int* __restrict__ out,
                               int E, int srcOffset)
{
    int i = blockIdx.x * blockDim.x + threadIdx.x;
    if (i >= E) return;
    int p = atomicAdd(&cursor[dst[i]], 1);
    out[p] = src[i] + srcOffset;
}

// ---------------- fused attention (both node types; merged Q|K|V half tables) ----
// Paper dest (gwarp < NP):  Q = P640[node*640 + c];
//   src sr < NA -> A384 row sr: K at +128+c, V at +256+c (prior rel0)
//   src sr >= NA -> P640 row sr-NA: K at +128+c, V at +256+c (prior rel2)
// Author dest: Q = A384[node*384 + c]; src paper s -> P640 row s: K at +384+c, V at +512+c (rel1)
__global__ void attn_agg2(const __half* __restrict__ A384, const __half* __restrict__ P640,
                          const int* __restrict__ rowP, const int* __restrict__ srcP,
                          const float* __restrict__ prel0, const float* __restrict__ prel2,
                          const int* __restrict__ rowA, const int* __restrict__ srcA,
                          const float* __restrict__ prel1,
                          float* __restrict__ aggP, float* __restrict__ aggA)
{
    int gwarp = (blockIdx.x * blockDim.x + threadIdx.x) >> 5;
    int lane = threadIdx.x & 31;
    if (gwarp >= NP + NA) return;
    int h = lane >> 2;
    int c = h * 16 + (lane & 3) * 4;

    float m = -INFINITY, s = 0.f;
    float4 acc = make_float4(0.f, 0.f, 0.f, 0.f);

    if (gwarp < NP) {
        int node = gwarp;
        float4 q4 = ld4h(P640 + (size_t)node * 640 + c);
        float pA = prel0[h] * 0.25f;
        float pB = prel2[h] * 0.25f;
        int js = rowP[node], je = rowP[node + 1];
        int j = js;
        for (; j + 1 < je; j += 2) {
            int sr1 = srcP[j];
            int sr2 = srcP[j + 1];
            const __half* kv1 = (sr1 < NA) ? (A384 + (size_t)sr1 * 384 + 128)
                                           : (P640 + (size_t)(sr1 - NA) * 640 + 128);
            const __half* kv2 = (sr2 < NA) ? (A384 + (size_t)sr2 * 384 + 128)
                                           : (P640 + (size_t)(sr2 - NA) * 640 + 128);
            float4 k1 = ld4h(kv1 + c);
            float4 k2 = ld4h(kv2 + c);
            float p1 = q4.x * k1.x + q4.y * k1.y + q4.z * k1.z + q4.w * k1.w;
            float p2 = q4.x * k2.x + q4.y * k2.y + q4.z * k2.z + q4.w * k2.w;
            p1 += __shfl_xor_sync(0xffffffffu, p1, 1);
            p2 += __shfl_xor_sync(0xffffffffu, p2, 1);
            p1 += __shfl_xor_sync(0xffffffffu, p1, 2);
            p2 += __shfl_xor_sync(0xffffffffu, p2, 2);
            float a1 = p1 * ((sr1 < NA) ? pA : pB);
            float a2 = p2 * ((sr2 < NA) ? pA : pB);
            float4 v1 = ld4h(kv1 + 128 + c);
            float4 v2 = ld4h(kv2 + 128 + c);
            float newm = fmaxf(m, fmaxf(a1, a2));
            float scl = __expf(m - newm);
            float w1 = __expf(a1 - newm);
            float w2 = __expf(a2 - newm);
            s = s * scl + w1 + w2;
            acc.x = acc.x * scl + w1 * v1.x + w2 * v2.x;
            acc.y = acc.y * scl + w1 * v1.y + w2 * v2.y;
            acc.z = acc.z * scl + w1 * v1.z + w2 * v2.z;
            acc.w = acc.w * scl + w1 * v1.w + w2 * v2.w;
            m = newm;
        }
        for (; j < je; j++) {
            int sr = srcP[j];
            const __half* kv = (sr < NA) ? (A384 + (size_t)sr * 384 + 128)
                                         : (P640 + (size_t)(sr - NA) * 640 + 128);
            float4 k1 = ld4h(kv + c);
            float part = q4.x * k1.x + q4.y * k1.y + q4.z * k1.z + q4.w * k1.w;
            part += __shfl_xor_sync(0xffffffffu, part, 1);
            part += __shfl_xor_sync(0xffffffffu, part, 2);
            float a = part * ((sr < NA) ? pA : pB);
            float newm = fmaxf(m, a);
            float scl = __expf(m - newm);
            float w = __expf(a - newm);
            s = s * scl + w;
            float4 v1 = ld4h(kv + 128 + c);
            acc.x = acc.x * scl + w * v1.x;
            acc.y = acc.y * scl + w * v1.y;
            acc.z = acc.z * scl + w * v1.z;
            acc.w = acc.w * scl + w * v1.w;
            m = newm;
        }
        float inv = 1.f / (s + 1e-16f);
        float4 r;
        float v;
        v = acc.x * inv; r.x = 0.5f * v * (1.f + erff(v * 0.70710678118654752f));
        v = acc.y * inv; r.y = 0.5f * v * (1.f + erff(v * 0.70710678118654752f));
        v = acc.z * inv; r.z = 0.5f * v * (1.f + erff(v * 0.70710678118654752f));
        v = acc.w * inv; r.w = 0.5f * v * (1.f + erff(v * 0.70710678118654752f));
        *(float4*)(aggP + (size_t)node * 128 + c) = r;
    } else {
        int node = gwarp - NP;
        float4 q4 = ld4h(A384 + (size_t)node * 384 + c);
        float pr = prel1[h] * 0.25f;
        int js = rowA[node], je = rowA[node + 1];
        int j = js;
        for (; j + 1 < je; j += 2) {
            int s1 = srcA[j];
            int s2 = srcA[j + 1];
            const __half* kv1 = P640 + (size_t)s1 * 640 + 384;
            const __half* kv2 = P640 + (size_t)s2 * 640 + 384;
            float4 k1 = ld4h(kv1 + c);
            float4 k2 = ld4h(kv2 + c);
            float p1 = q4.x * k1.x + q4.y * k1.y + q4.z * k1.z + q4.w * k1.w;
            float p2 = q4.x * k2.x + q4.y * k2.y + q4.z * k2.z + q4.w * k2.w;
            p1 += __shfl_xor_sync(0xffffffffu, p1, 1);
            p2 += __shfl_xor_sync(0xffffffffu, p2, 1);
            p1 += __shfl_xor_sync(0xffffffffu, p1, 2);
            p2 += __shfl_xor_sync(0xffffffffu, p2, 2);
            float a1 = p1 * pr;
            float a2 = p2 * pr;
            float4 v1 = ld4h(kv1 + 128 + c);
            float4 v2 = ld4h(kv2 + 128 + c);
            float newm = fmaxf(m, fmaxf(a1, a2));
            float scl = __expf(m - newm);
            float w1 = __expf(a1 - newm);
            float w2 = __expf(a2 - newm);
            s = s * scl + w1 + w2;
            acc.x = acc.x * scl + w1 * v1.x + w2 * v2.x;
            acc.y = acc.y * scl + w1 * v1.y + w2 * v2.y;
            acc.z = acc.z * scl + w1 * v1.z + w2 * v2.z;
            acc.w = acc.w * scl + w1 * v1.w + w2 * v2.w;
            m = newm;
        }
        for (; j < je; j++) {
            int s1 = srcA[j];
            const __half* kv = P640 + (size_t)s1 * 640 + 384;
            float4 k1 = ld4h(kv + c);
            float part = q4.x * k1.x + q4.y * k1.y + q4.z * k1.z + q4.w * k1.w;
            part += __shfl_xor_sync(0xffffffffu, part, 1);
            part += __shfl_xor_sync(0xffffffffu, part, 2);
            float a = part * pr;
            float newm = fmaxf(m, a);
            float scl = __expf(m - newm);
            float w = __expf(a - newm);
            s = s * scl + w;
            float4 v1 = ld4h(kv + 128 + c);
            acc.x = acc.x * scl + w * v1.x;
            acc.y = acc.y * scl + w * v1.y;
            acc.z = acc.z * scl + w * v1.z;
            acc.w = acc.w * scl + w * v1.w;
            m = newm;
        }
        float inv = 1.f / (s + 1e-16f);
        float4 r;
        float v;
        v = acc.x * inv; r.x = 0.5f * v * (1.f + erff(v * 0.70710678118654752f));
        v = acc.y * inv; r.y = 0.5f * v * (1.f + erff(v * 0.70710678118654752f));
        v = acc.z * inv; r.z = 0.5f * v * (1.f + erff(v * 0.70710678118654752f));
        v = acc.w * inv; r.w = 0.5f * v * (1.f + erff(v * 0.70710678118654752f));
        *(float4*)(aggA + (size_t)node * 128 + c) = r;
    }
}

// ---------------- BatchNorm (standalone; both node types per launch) ----------------
__global__ void bn_stats2(const float* __restrict__ hA, const float* __restrict__ hP,
                          float* __restrict__ stats)   // [0:256) author, [256:512) paper
{
    int c = threadIdx.x;
    const int nbA = (NA + 255) / 256;
    float s = 0.f, s2 = 0.f;
    if ((int)blockIdx.x < nbA) {
        int r0 = blockIdx.x * 256;
        int r1 = min(NA, r0 + 256);
        for (int r = r0; r < r1; r++) {
            float v = hA[(size_t)r * 128 + c];
            s += v; s2 += v * v;
        }
        atomicAdd(&stats[c], s);
        atomicAdd(&stats[128 + c], s2);
    } else {
        int r0 = (blockIdx.x - nbA) * 256;
        int r1 = min(NP, r0 + 256);
        for (int r = r0; r < r1; r++) {
            float v = hP[(size_t)r * 128 + c];
            s += v; s2 += v * v;
        }
        atomicAdd(&stats[256 + c], s);
        atomicAdd(&stats[256 + 128 + c], s2);
    }
}

__global__ void bn_apply2(const float* __restrict__ hA, const float* __restrict__ hP,
                          const float* __restrict__ stats,
                          const float* __restrict__ gamma, const float* __restrict__ beta,
                          float* __restrict__ outA, float* __restrict__ outP)
{
    int i = blockIdx.x * blockDim.x + threadIdx.x;
    const int totA = NA * 128;
    const int totP = NP * 128;
    if (i < totA) {
        int c = i & 127;
        float invN = 1.f / (float)NA;
        float mu = stats[c] * invN;
        float var = stats[128 + c] * invN - mu * mu;
        outA[i] = (hA[i] - mu) * rsqrtf(var + BN_EPS) * gamma[c] + beta[c];
    } else {
        int k = i - totA;
        if (k >= totP) return;
        int c = k & 127;
        float invN = 1.f / (float)NP;
        float mu = stats[256 + c] * invN;
        float var = stats[256 + 128 + c] * invN - mu * mu;
        outP[k] = (hP[k] - mu) * rsqrtf(var + BN_EPS) * gamma[c] + beta[c];
    }
}

// ---------------------------------------------------------------
static inline int cdiv(long long a, long long b) { return (int)((a + b - 1) / b); }

extern "C" void kernel_launch(void* const* d_in, const int* in_sizes, int n_in,
                              void* d_out, int out_size)
{
    const float* x_author = (const float*)d_in[0];
    const float* x_paper  = (const float*)d_in[1];
    const int* writes_src = (const int*)d_in[2];
    const int* writes_dst = (const int*)d_in[3];
    const int* rev_src    = (const int*)d_in[4];
    const int* rev_dst    = (const int*)d_in[5];
    const int* cites_src  = (const int*)d_in[6];
    const int* cites_dst  = (const int*)d_in[7];
    const float* linA_W   = (const float*)d_in[8];
    const float* linA_b   = (const float*)d_in[9];
    const float* linP_W   = (const float*)d_in[10];
    const float* linP_b   = (const float*)d_in[11];
    const float* kqv_W    = (const float*)d_in[12];
    const float* kqv_b    = (const float*)d_in[13];
    const float* a_k      = (const float*)d_in[14];
    const float* a_v      = (const float*)d_in[15];
    const float* p_rel    = (const float*)d_in[16];
    const float* out_W    = (const float*)d_in[17];
    const float* out_b    = (const float*)d_in[18];
    const float* skipP    = (const float*)d_in[19];
    const float* bn_gamma = (const float*)d_in[20];
    const float* bn_beta  = (const float*)d_in[21];

    float* base = nullptr;
    cudaGetSymbolAddress((void**)&base, g_scratch);

    float* XA    = base + OFF_XA;
    float* XP    = base + OFF_XP;
    __half* A384 = (__half*)(base + OFF_A384);
    __half* P640 = (__half*)(base + OFF_P640);
    float* AGGA  = base + OFF_AGGA;
    float* AGGP  = base + OFF_AGGP;
    float* TMPA  = base + OFF_TMPA;
    float* TMPP  = base + OFF_TMPP;
    float* WA    = base + OFF_WA;
    float* WP    = base + OFF_WP;
    float* WAB   = base + OFF_WAB;
    float* WPB   = base + OFF_WPB;
    float* STA   = base + OFF_STATS;        // [0:256) author, [256:512) paper
    int* ibase   = (int*)(base + OFF_INT);
    int* ROWP    = ibase + IOFF_ROWP;
    int* ROWA    = ibase + IOFF_ROWA;
    int* CURP    = ibase + IOFF_CURP;
    int* CURA    = ibase + IOFF_CURA;
    int* SRCP    = ibase + IOFF_SRCP;
    int* SRCA    = ibase + IOFF_SRCA;
    int* BS      = ibase + IOFF_BS;

    // -------- CSR build + composite weights (x-independent) --------
    const int nbP = cdiv(NP, 1024), nbA = cdiv(NA, 1024);
    cudaMemsetAsync(CURP, 0, (size_t)NP * 4, 0);
    cudaMemsetAsync(CURA, 0, (size_t)NA * 4, 0);
    hist_kernel<<<cdiv(EW, 256), 256>>>(writes_dst, CURP, EW);
    hist_kernel<<<cdiv(EC, 256), 256>>>(cites_dst, CURP, EC);
    hist_kernel<<<cdiv(ER, 256), 256>>>(rev_dst, CURA, ER);
    scan_partial<<<nbP, 256>>>(CURP, ROWP, BS, NP);
    scan_small<<<1, 256>>>(BS, nbP);
    add_off<<<cdiv(NP, 256), 256>>>(ROWP, CURP, BS, NP, nbP);
    scan_partial<<<nbA, 256>>>(CURA, ROWA, BS, NA);
    scan_small<<<1, 256>>>(BS, nbA);
    add_off<<<cdiv(NA, 256), 256>>>(ROWA, CURA, BS, NA, nbA);
    scatter_kernel<<<cdiv(EW, 256), 256>>>(writes_src, writes_dst, CURP, SRCP, EW, 0);
    scatter_kernel<<<cdiv(EC, 256), 256>>>(cites_src, cites_dst, CURP, SRCP, EC, NA);
    scatter_kernel<<<cdiv(ER, 256), 256>>>(rev_src, rev_dst, CURA, SRCA, ER, 0);
    wcompA<<<cdiv(2 * 128 * 384, 256), 256>>>(kqv_W, a_k, a_v, WA);
    wcompP<<<cdiv(2 * 128 * 640, 256), 256>>>(kqv_W, a_k, a_v, WP);
    bcompA<<<3, 256>>>(kqv_b, a_k, a_v, WAB);
    bcompP<<<5, 256>>>(kqv_b, a_k, a_v, WPB);

    // -------- input projections + relu --------
    gemm_tf32<<<dim3(1, cdiv(NA, 128)), 256>>>(x_author, 128, linA_W, 128, linA_b,
                                               XA, nullptr, 128, NA, 128, 1, nullptr, nullptr);
    gemm_tf32<<<dim3(1, cdiv(NP, 128)), 256>>>(x_paper, 128, linP_W, 128, linP_b,
                                               XP, nullptr, 128, NP, 128, 1, nullptr, nullptr);

    for (int l = 0; l < 2; l++) {
        // merged Q|K|V projections, fp16 output
        gemm_tf32<<<dim3(3, cdiv(NA, 128)), 256>>>(XA, 128, WA + (size_t)l * 128 * 384, 384,
                                                   WAB + (size_t)l * 384,
                                                   nullptr, A384, 384, NA, 128, 0, nullptr, nullptr);
        gemm_tf32<<<dim3(5, cdiv(NP, 128)), 256>>>(XP, 128, WP + (size_t)l * 128 * 640, 640,
                                                   WPB + (size_t)l * 640,
                                                   nullptr, P640, 640, NP, 128, 0, nullptr, nullptr);

        // fused attention + softmax + aggregation + gelu (single launch, both types)
        attn_agg2<<<cdiv((long long)(NP + NA) * 32, 256), 256>>>(
            A384, P640,
            ROWP, SRCP, p_rel + (size_t)(l * 3 + 0) * NH, p_rel + (size_t)(l * 3 + 2) * NH,
            ROWA, SRCA, p_rel + (size_t)(l * 3 + 1) * NH,
            AGGP, AGGA);

        // output projection + fused sigmoid-skip mix (lean GEMM)
        gemm_tf32<<<dim3(1, cdiv(NA, 128)), 256>>>(AGGA, 128, out_W + (size_t)(l * 2 + 0) * 128 * 128, 128,
                                                   out_b + (size_t)(l * 2 + 0) * 128,
                                                   TMPA, nullptr, 128, NA, 128, 2, XA, skipP + (l * 2 + 0));
        gemm_tf32<<<dim3(1, cdiv(NP, 128)), 256>>>(AGGP, 128, out_W + (size_t)(l * 2 + 1) * 128 * 128, 128,
                                                   out_b + (size_t)(l * 2 + 1) * 128,
                                                   TMPP, nullptr, 128, NP, 128, 2, XP, skipP + (l * 2 + 1));

        // batch norm: stats then apply, both node types per launch
        cudaMemsetAsync(STA, 0, 512 * 4, 0);
        bn_stats2<<<cdiv(NA, 256) + cdiv(NP, 256), 128>>>(TMPA, TMPP, STA);
        float* outA = (l == 1) ? (float*)d_out : XA;
        float* outP = (l == 1) ? (float*)d_out + (size_t)NA * 128 : XP;
        bn_apply2<<<cdiv((long long)(NA + NP) * 128, 256), 256>>>(TMPA, TMPP, STA,
                                                                  bn_gamma + (size_t)l * 128,
                                                                  bn_beta + (size_t)l * 128,
                                                                  outA, outP);
    }
}

// round 14
// speedup vs baseline: 1.1359x; 1.0487x over previous
#include <cuda_runtime.h>
#include <cuda_fp16.h>
#include <math.h>
#include <stdint.h>

// ---------------- problem sizes ----------------
#define NA 50000
#define NP 100000
#define HC 128
#define NH 8
#define EW 400000
#define ER 400000
#define EC 800000
#define EP (EW + EC)
#define BN_EPS 1e-5f

// ---------------- scratch layout (float units) ----------------
#define OFF_XA    0ull
#define OFF_XP    (OFF_XA   + (size_t)NA*128)
#define OFF_A384  (OFF_XP   + (size_t)NP*128)        // half[NA*384] : Q | K_rel0 | V_rel0
#define OFF_P640  (OFF_A384 + (size_t)NA*192)        // half[NP*640] : Q | K_rel2 | V_rel2 | K_rel1 | V_rel1
#define OFF_AGGA  (OFF_P640 + (size_t)NP*320)
#define OFF_AGGP  (OFF_AGGA + (size_t)NA*128)
#define OFF_TMPA  (OFF_AGGP + (size_t)NP*128)
#define OFF_TMPP  (OFF_TMPA + (size_t)NA*128)
#define OFF_WA    (OFF_TMPP + (size_t)NP*128)        // 2 * 128 * 384
#define OFF_WP    (OFF_WA   + 2ull*128*384)          // 2 * 128 * 640
#define OFF_WAB   (OFF_WP   + 2ull*128*640)          // 2 * 384
#define OFF_WPB   (OFF_WAB  + 2ull*384)              // 2 * 640
#define OFF_STATS (OFF_WPB  + 2ull*640)
// integer region
#define OFF_INT   (OFF_STATS + 512ull)
#define IOFF_ROWP 0ull
#define IOFF_ROWA (IOFF_ROWP + NP + 1)
#define IOFF_CURP (IOFF_ROWA + NA + 1)
#define IOFF_CURA (IOFF_CURP + NP)
#define IOFF_SRCP (IOFF_CURA + NA)
#define IOFF_SRCA (IOFF_SRCP + EP)
#define IOFF_BS   (IOFF_SRCA + ER)
#define INT_TOTAL (IOFF_BS + 256)
#define TOTAL_FLOATS (OFF_INT + INT_TOTAL + 64ull)

__device__ float g_scratch[TOTAL_FLOATS];

// ---------------- tf32 helpers ----------------
__device__ __forceinline__ uint32_t f2tf32(float x)
{
    uint32_t r;
    asm("cvt.rna.tf32.f32 %0, %1;" : "=r"(r) : "f"(x));
    return r;
}

__device__ __forceinline__ void mma_tf32(float4& c, const uint32_t* a, const uint32_t* b)
{
    asm volatile(
        "mma.sync.aligned.m16n8k8.row.col.f32.tf32.tf32.f32 "
        "{%0,%1,%2,%3}, {%4,%5,%6,%7}, {%8,%9}, {%0,%1,%2,%3};"
        : "+f"(c.x), "+f"(c.y), "+f"(c.z), "+f"(c.w)
        : "r"(a[0]), "r"(a[1]), "r"(a[2]), "r"(a[3]), "r"(b[0]), "r"(b[1]));
}

__device__ __forceinline__ float4 ld4h(const __half* p)
{
    __half2 a = *(const __half2*)p;
    __half2 b = *(const __half2*)(p + 2);
    float2 fa = __half22float2(a), fb = __half22float2(b);
    return make_float4(fa.x, fa.y, fb.x, fb.y);
}

// ---------------- dual-problem tf32x2 GEMM (R13 mainloop byte-identical) --------
// Two independent problems in one launch, split by blockIdx.y < gy1.
// Per problem: C[M,*] = A[M,K] @ W[K,*] + bias; Ch != nullptr -> fp16 output.
// act: 0=none, 1=relu, 2=skip-mix. K=128 for all call sites.
__global__ void __launch_bounds__(256)
gemm2(const float* __restrict__ A0, int lda0, const float* __restrict__ W0, int ldw0,
      const float* __restrict__ b0, float* __restrict__ C0, __half* __restrict__ Ch0,
      int ldc0, int M0, int gx0, const float* __restrict__ x0, const float* __restrict__ s0,
      const float* __restrict__ A1, int lda1, const float* __restrict__ W1, int ldw1,
      const float* __restrict__ b1, float* __restrict__ C1, __half* __restrict__ Ch1,
      int ldc1, int M1, int gx1, const float* __restrict__ x1, const float* __restrict__ s1,
      int gy1, int act)
{
    __shared__ uint32_t As[128][20];
    __shared__ uint32_t Bs[16][136], Bl[16][136];

    // uniform problem select
    const float* A; const float* W; const float* bias; float* C; __half* Ch;
    const float* xold; const float* skipv;
    int lda, ldw, ldc, M, gx, bm;
    if ((int)blockIdx.y < gy1) {
        A = A0; W = W0; bias = b0; C = C0; Ch = Ch0; xold = x0; skipv = s0;
        lda = lda0; ldw = ldw0; ldc = ldc0; M = M0; gx = gx0;
        bm = blockIdx.y * 128;
    } else {
        A = A1; W = W1; bias = b1; C = C1; Ch = Ch1; xold = x1; skipv = s1;
        lda = lda1; ldw = ldw1; ldc = ldc1; M = M1; gx = gx1;
        bm = (blockIdx.y - gy1) * 128;
    }
    if ((int)blockIdx.x >= gx) return;

    const int bn = blockIdx.x * 128;
    const int tid = threadIdx.x;
    const int lane = tid & 31;
    const int warp = tid >> 5;
    const int wm = warp >> 2;
    const int wn = warp & 3;

    float4 acc[4][4];
#pragma unroll
    for (int i = 0; i < 4; i++)
#pragma unroll
        for (int j = 0; j < 4; j++) acc[i][j] = make_float4(0.f, 0.f, 0.f, 0.f);

    for (int k0 = 0; k0 < 128; k0 += 16) {
#pragma unroll
        for (int i = 0; i < 2; i++) {
            int id  = tid + i * 256;
            int row = id >> 2;
            int kc  = (id & 3) * 4;
            int grow = bm + row;
            float4 v = make_float4(0.f, 0.f, 0.f, 0.f);
            if (grow < M) v = *(const float4*)(A + (size_t)grow * lda + k0 + kc);
            As[row][kc + 0] = f2tf32(v.x); As[row][kc + 1] = f2tf32(v.y);
            As[row][kc + 2] = f2tf32(v.z); As[row][kc + 3] = f2tf32(v.w);
        }
#pragma unroll
        for (int i = 0; i < 2; i++) {
            int id  = tid + i * 256;
            int row = id >> 5;
            int col = (id & 31) * 4;
            float4 v = *(const float4*)(W + (size_t)(k0 + row) * ldw + bn + col);
            uint32_t h;
            h = f2tf32(v.x); Bs[row][col + 0] = h; Bl[row][col + 0] = f2tf32(v.x - __uint_as_float(h));
            h = f2tf32(v.y); Bs[row][col + 1] = h; Bl[row][col + 1] = f2tf32(v.y - __uint_as_float(h));
            h = f2tf32(v.z); Bs[row][col + 2] = h; Bl[row][col + 2] = f2tf32(v.z - __uint_as_float(h));
            h = f2tf32(v.w); Bs[row][col + 3] = h; Bl[row][col + 3] = f2tf32(v.w - __uint_as_float(h));
        }
        __syncthreads();

#pragma unroll
        for (int ks = 0; ks < 16; ks += 8) {
            uint32_t af[4][4];
            const int kc = ks + (lane & 3);
#pragma unroll
            for (int mf = 0; mf < 4; mf++) {
                int r = wm * 64 + mf * 16 + (lane >> 2);
                af[mf][0] = As[r][kc];
                af[mf][1] = As[r + 8][kc];
                af[mf][2] = As[r][kc + 4];
                af[mf][3] = As[r + 8][kc + 4];
            }
            uint32_t bh[4][2], bl[4][2];
#pragma unroll
            for (int nf = 0; nf < 4; nf++) {
                int n = wn * 32 + nf * 8 + (lane >> 2);
                bh[nf][0] = Bs[kc][n];     bl[nf][0] = Bl[kc][n];
                bh[nf][1] = Bs[kc + 4][n]; bl[nf][1] = Bl[kc + 4][n];
            }
#pragma unroll
            for (int mf = 0; mf < 4; mf++)
#pragma unroll
                for (int nf = 0; nf < 4; nf++) {
                    mma_tf32(acc[mf][nf], af[mf], bl[nf]);
                    mma_tf32(acc[mf][nf], af[mf], bh[nf]);
                }
        }
        __syncthreads();
    }

    const int lr = lane >> 2;
    const int lc = (lane & 3) * 2;
    float sk = 0.f;
    if (act == 2) sk = 1.f / (1.f + __expf(-skipv[0]));
    float2 bv[4];
#pragma unroll
    for (int nf = 0; nf < 4; nf++) {
        int c0 = bn + wn * 32 + nf * 8 + lc;
        bv[nf] = *(const float2*)(bias + c0);
    }
#pragma unroll
    for (int mf = 0; mf < 4; mf++) {
        int r0 = bm + wm * 64 + mf * 16 + lr;
        int r1 = r0 + 8;
#pragma unroll
        for (int nf = 0; nf < 4; nf++) {
            int c0 = bn + wn * 32 + nf * 8 + lc;
            float4 a = acc[mf][nf];
            float2 o0 = make_float2(a.x + bv[nf].x, a.y + bv[nf].y);
            float2 o1 = make_float2(a.z + bv[nf].x, a.w + bv[nf].y);
            if (act == 1) {
                o0.x = fmaxf(o0.x, 0.f); o0.y = fmaxf(o0.y, 0.f);
                o1.x = fmaxf(o1.x, 0.f); o1.y = fmaxf(o1.y, 0.f);
            } else if (act == 2) {
                if (r0 < M) {
                    float2 xv = *(const float2*)(xold + (size_t)r0 * ldc + c0);
                    o0.x = sk * o0.x + (1.f - sk) * xv.x;
                    o0.y = sk * o0.y + (1.f - sk) * xv.y;
                }
                if (r1 < M) {
                    float2 xv = *(const float2*)(xold + (size_t)r1 * ldc + c0);
                    o1.x = sk * o1.x + (1.f - sk) * xv.x;
                    o1.y = sk * o1.y + (1.f - sk) * xv.y;
                }
            }
            if (Ch) {
                if (r0 < M) *(__half2*)(Ch + (size_t)r0 * ldc + c0) = __floats2half2_rn(o0.x, o0.y);
                if (r1 < M) *(__half2*)(Ch + (size_t)r1 * ldc + c0) = __floats2half2_rn(o1.x, o1.y);
            } else {
                if (r0 < M) *(float2*)(C + (size_t)r0 * ldc + c0) = o0;
                if (r1 < M) *(float2*)(C + (size_t)r1 * ldc + c0) = o1;
            }
        }
    }
}

// ---------------- composite weights: author [128x384], paper [128x640] --------
__global__ void wcompA(const float* __restrict__ kqv_W, const float* __restrict__ a_k,
                       const float* __restrict__ a_v, float* __restrict__ WA)
{
    int gid = blockIdx.x * blockDim.x + threadIdx.x;
    if (gid >= 2 * 128 * 384) return;
    int l = gid / (128 * 384);
    int rem = gid % (128 * 384);
    int r = rem / 384, c = rem % 384;
    const float* Wrow = kqv_W + (size_t)(l * 2 + 0) * 128 * 384 + (size_t)r * 384;
    float s;
    if (c < 128) {
        s = Wrow[128 + c];
    } else {
        int cc = c - 128;
        int c2 = cc & 127, h = c2 >> 4, e = c2 & 15;
        const float* Wb = Wrow + ((cc < 128) ? 0 : 256);
        const float* Am = ((cc < 128) ? a_k : a_v) + (size_t)(l * 3 + 0) * 2048 + h * 256 + e;
        s = 0.f;
#pragma unroll
        for (int dd = 0; dd < 16; dd++) s += Wb[h * 16 + dd] * Am[dd * 16];
    }
    WA[gid] = s;
}

__global__ void wcompP(const float* __restrict__ kqv_W, const float* __restrict__ a_k,
                       const float* __restrict__ a_v, float* __restrict__ WP)
{
    int gid = blockIdx.x * blockDim.x + threadIdx.x;
    if (gid >= 2 * 128 * 640) return;
    int l = gid / (128 * 640);
    int rem = gid % (128 * 640);
    int r = rem / 640, c = rem % 640;
    const float* Wrow = kqv_W + (size_t)(l * 2 + 1) * 128 * 384 + (size_t)r * 384;
    float s;
    if (c < 128) {
        s = Wrow[128 + c];
    } else {
        int rel = (c < 384) ? 2 : 1;
        int cc = (c < 384) ? (c - 128) : (c - 384);
        int c2 = cc & 127, h = c2 >> 4, e = c2 & 15;
        const float* Wb = Wrow + ((cc < 128) ? 0 : 256);
        const float* Am = ((cc < 128) ? a_k : a_v) + (size_t)(l * 3 + rel) * 2048 + h * 256 + e;
        s = 0.f;
#pragma unroll
        for (int dd = 0; dd < 16; dd++) s += Wb[h * 16 + dd] * Am[dd * 16];
    }
    WP[gid] = s;
}

__global__ void bcompA(const float* __restrict__ kqv_b, const float* __restrict__ a_k,
                       const float* __restrict__ a_v, float* __restrict__ WAB)
{
    int gid = blockIdx.x * blockDim.x + threadIdx.x;
    if (gid >= 2 * 384) return;
    int l = gid / 384, c = gid % 384;
    const float* brow = kqv_b + (size_t)(l * 2 + 0) * 384;
    float s;
    if (c < 128) {
        s = brow[128 + c];
    } else {
        int cc = c - 128;
        int c2 = cc & 127, h = c2 >> 4, e = c2 & 15;
        const float* bb = brow + ((cc < 128) ? 0 : 256);
        const float* Am = ((cc < 128) ? a_k : a_v) + (size_t)(l * 3 + 0) * 2048 + h * 256 + e;
        s = 0.f;
#pragma unroll
        for (int dd = 0; dd < 16; dd++) s += bb[h * 16 + dd] * Am[dd * 16];
    }
    WAB[gid] = s;
}

__global__ void bcompP(const float* __restrict__ kqv_b, const float* __restrict__ a_k,
                       const float* __restrict__ a_v, float* __restrict__ WPB)
{
    int gid = blockIdx.x * blockDim.x + threadIdx.x;
    if (gid >= 2 * 640) return;
    int l = gid / 640, c = gid % 640;
    const float* brow = kqv_b + (size_t)(l * 2 + 1) * 384;
    float s;
    if (c < 128) {
        s = brow[128 + c];
    } else {
        int rel = (c < 384) ? 2 : 1;
        int cc = (c < 384) ? (c - 128) : (c - 384);
        int c2 = cc & 127, h = c2 >> 4, e = c2 & 15;
        const float* bb = brow + ((cc < 128) ? 0 : 256);
        const float* Am = ((cc < 128) ? a_k : a_v) + (size_t)(l * 3 + rel) * 2048 + h * 256 + e;
        s = 0.f;
#pragma unroll
        for (int dd = 0; dd < 16; dd++) s += bb[h * 16 + dd] * Am[dd * 16];
    }
    WPB[gid] = s;
}

// ---------------- CSR build ----------------
__global__ void hist_kernel(const int* __restrict__ dst, int* __restrict__ deg, int E)
{
    int i = blockIdx.x * blockDim.x + threadIdx.x;
    if (i < E) atomicAdd(&deg[dst[i]], 1);
}

__global__ void scan_partial(const int* __restrict__ deg, int* __restrict__ row,
                             int* __restrict__ bsums, int n)
{
    __shared__ int warpsum[8];
    int t = threadIdx.x;
    int lane = t & 31, wid = t >> 5;
    int base = blockIdx.x * 1024 + t * 4;
    int v0 = (base + 0 < n) ? deg[base + 0] : 0;
    int v1 = (base + 1 < n) ? deg[base + 1] : 0;
    int v2 = (base + 2 < n) ? deg[base + 2] : 0;
    int v3 = (base + 3 < n) ? deg[base + 3] : 0;
    int e0 = 0, e1 = v0, e2 = e1 + v1, e3 = e2 + v2;
    int tot = e3 + v3;
    int inc = tot;
#pragma unroll
    for (int off = 1; off < 32; off <<= 1) {
        int y = __shfl_up_sync(0xffffffffu, inc, off);
        if (lane >= off) inc += y;
    }
    if (lane == 31) warpsum[wid] = inc;
    __syncthreads();
    if (wid == 0) {
        int w = (lane < 8) ? warpsum[lane] : 0;
#pragma unroll
        for (int off = 1; off < 8; off <<= 1) {
            int y = __shfl_up_sync(0xffffffffu, w, off);
            if (lane >= off) w += y;
        }
        if (lane < 8) warpsum[lane] = w;
    }
    __syncthreads();
    int warpExcl = (wid == 0) ? 0 : warpsum[wid - 1];
    int thrExcl = warpExcl + inc - tot;
    if (base + 0 < n) row[base + 0] = thrExcl + e0;
    if (base + 1 < n) row[base + 1] = thrExcl + e1;
    if (base + 2 < n) row[base + 2] = thrExcl + e2;
    if (base + 3 < n) row[base + 3] = thrExcl + e3;
    if (t == 0) bsums[blockIdx.x] = warpsum[7];
}

__global__ void scan_small(int* __restrict__ bsums, int nb)
{
    __shared__ int warpsum[8];
    int t = threadIdx.x;
    int lane = t & 31, wid = t >> 5;
    int v = (t < nb) ? bsums[t] : 0;
    int inc = v;
#pragma unroll
    for (int off = 1; off < 32; off <<= 1) {
        int y = __shfl_up_sync(0xffffffffu, inc, off);
        if (lane >= off) inc += y;
    }
    if (lane == 31) warpsum[wid] = inc;
    __syncthreads();
    if (wid == 0) {
        int w = (lane < 8) ? warpsum[lane] : 0;
#pragma unroll
        for (int off = 1; off < 8; off <<= 1) {
            int y = __shfl_up_sync(0xffffffffu, w, off);
            if (lane >= off) w += y;
        }
        if (lane < 8) warpsum[lane] = w;
    }
    __syncthreads();
    int warpExcl = (wid == 0) ? 0 : warpsum[wid - 1];
    int excl = warpExcl + inc - v;
    if (t < nb) bsums[t] = excl;
    if (t == 255) bsums[nb] = warpExcl + inc;
}

__global__ void add_off(int* __restrict__ row, int* __restrict__ cur,
                        const int* __restrict__ bsums, int n, int nb)
{
    int i = blockIdx.x * blockDim.x + threadIdx.x;
    if (i < n) {
        int r = row[i] + bsums[i >> 10];
        row[i] = r;
        cur[i] = r;
    }
    if (i == 0) row[n] = bsums[nb];
}

__global__ void scatter_kernel(const int* __restrict__ src, const int* __restrict__ dst,
                               int* __restrict__ cursor, int* __restrict__ out,
                               int E, int srcOffset)
{
    int i = blockIdx.x * blockDim.x + threadIdx.x;
    if (i >= E) return;
    int p = atomicAdd(&cursor[dst[i]], 1);
    out[p] = src[i] + srcOffset;
}

// ---------------- fused attention (both node types; merged Q|K|V half tables) ----
__global__ void attn_agg2(const __half* __restrict__ A384, const __half* __restrict__ P640,
                          const int* __restrict__ rowP, const int* __restrict__ srcP,
                          const float* __restrict__ prel0, const float* __restrict__ prel2,
                          const int* __restrict__ rowA, const int* __restrict__ srcA,
                          const float* __restrict__ prel1,
                          float* __restrict__ aggP, float* __restrict__ aggA)
{
    int gwarp = (blockIdx.x * blockDim.x + threadIdx.x) >> 5;
    int lane = threadIdx.x & 31;
    if (gwarp >= NP + NA) return;
    int h = lane >> 2;
    int c = h * 16 + (lane & 3) * 4;

    float m = -INFINITY, s = 0.f;
    float4 acc = make_float4(0.f, 0.f, 0.f, 0.f);

    if (gwarp < NP) {
        int node = gwarp;
        float4 q4 = ld4h(P640 + (size_t)node * 640 + c);
        float pA = prel0[h] * 0.25f;
        float pB = prel2[h] * 0.25f;
        int js = rowP[node], je = rowP[node + 1];
        int j = js;
        for (; j + 1 < je; j += 2) {
            int sr1 = srcP[j];
            int sr2 = srcP[j + 1];
            const __half* kv1 = (sr1 < NA) ? (A384 + (size_t)sr1 * 384 + 128)
                                           : (P640 + (size_t)(sr1 - NA) * 640 + 128);
            const __half* kv2 = (sr2 < NA) ? (A384 + (size_t)sr2 * 384 + 128)
                                           : (P640 + (size_t)(sr2 - NA) * 640 + 128);
            float4 k1 = ld4h(kv1 + c);
            float4 k2 = ld4h(kv2 + c);
            float p1 = q4.x * k1.x + q4.y * k1.y + q4.z * k1.z + q4.w * k1.w;
            float p2 = q4.x * k2.x + q4.y * k2.y + q4.z * k2.z + q4.w * k2.w;
            p1 += __shfl_xor_sync(0xffffffffu, p1, 1);
            p2 += __shfl_xor_sync(0xffffffffu, p2, 1);
            p1 += __shfl_xor_sync(0xffffffffu, p1, 2);
            p2 += __shfl_xor_sync(0xffffffffu, p2, 2);
            float a1 = p1 * ((sr1 < NA) ? pA : pB);
            float a2 = p2 * ((sr2 < NA) ? pA : pB);
            float4 v1 = ld4h(kv1 + 128 + c);
            float4 v2 = ld4h(kv2 + 128 + c);
            float newm = fmaxf(m, fmaxf(a1, a2));
            float scl = __expf(m - newm);
            float w1 = __expf(a1 - newm);
            float w2 = __expf(a2 - newm);
            s = s * scl + w1 + w2;
            acc.x = acc.x * scl + w1 * v1.x + w2 * v2.x;
            acc.y = acc.y * scl + w1 * v1.y + w2 * v2.y;
            acc.z = acc.z * scl + w1 * v1.z + w2 * v2.z;
            acc.w = acc.w * scl + w1 * v1.w + w2 * v2.w;
            m = newm;
        }
        for (; j < je; j++) {
            int sr = srcP[j];
            const __half* kv = (sr < NA) ? (A384 + (size_t)sr * 384 + 128)
                                         : (P640 + (size_t)(sr - NA) * 640 + 128);
            float4 k1 = ld4h(kv + c);
            float part = q4.x * k1.x + q4.y * k1.y + q4.z * k1.z + q4.w * k1.w;
            part += __shfl_xor_sync(0xffffffffu, part, 1);
            part += __shfl_xor_sync(0xffffffffu, part, 2);
            float a = part * ((sr < NA) ? pA : pB);
            float newm = fmaxf(m, a);
            float scl = __expf(m - newm);
            float w = __expf(a - newm);
            s = s * scl + w;
            float4 v1 = ld4h(kv + 128 + c);
            acc.x = acc.x * scl + w * v1.x;
            acc.y = acc.y * scl + w * v1.y;
            acc.z = acc.z * scl + w * v1.z;
            acc.w = acc.w * scl + w * v1.w;
            m = newm;
        }
        float inv = 1.f / (s + 1e-16f);
        float4 r;
        float v;
        v = acc.x * inv; r.x = 0.5f * v * (1.f + erff(v * 0.70710678118654752f));
        v = acc.y * inv; r.y = 0.5f * v * (1.f + erff(v * 0.70710678118654752f));
        v = acc.z * inv; r.z = 0.5f * v * (1.f + erff(v * 0.70710678118654752f));
        v = acc.w * inv; r.w = 0.5f * v * (1.f + erff(v * 0.70710678118654752f));
        *(float4*)(aggP + (size_t)node * 128 + c) = r;
    } else {
        int node = gwarp - NP;
        float4 q4 = ld4h(A384 + (size_t)node * 384 + c);
        float pr = prel1[h] * 0.25f;
        int js = rowA[node], je = rowA[node + 1];
        int j = js;
        for (; j + 1 < je; j += 2) {
            int s1 = srcA[j];
            int s2 = srcA[j + 1];
            const __half* kv1 = P640 + (size_t)s1 * 640 + 384;
            const __half* kv2 = P640 + (size_t)s2 * 640 + 384;
            float4 k1 = ld4h(kv1 + c);
            float4 k2 = ld4h(kv2 + c);
            float p1 = q4.x * k1.x + q4.y * k1.y + q4.z * k1.z + q4.w * k1.w;
            float p2 = q4.x * k2.x + q4.y * k2.y + q4.z * k2.z + q4.w * k2.w;
            p1 += __shfl_xor_sync(0xffffffffu, p1, 1);
            p2 += __shfl_xor_sync(0xffffffffu, p2, 1);
            p1 += __shfl_xor_sync(0xffffffffu, p1, 2);
            p2 += __shfl_xor_sync(0xffffffffu, p2, 2);
            float a1 = p1 * pr;
            float a2 = p2 * pr;
            float4 v1 = ld4h(kv1 + 128 + c);
            float4 v2 = ld4h(kv2 + 128 + c);
            float newm = fmaxf(m, fmaxf(a1, a2));
            float scl = __expf(m - newm);
            float w1 = __expf(a1 - newm);
            float w2 = __expf(a2 - newm);
            s = s * scl + w1 + w2;
            acc.x = acc.x * scl + w1 * v1.x + w2 * v2.x;
            acc.y = acc.y * scl + w1 * v1.y + w2 * v2.y;
            acc.z = acc.z * scl + w1 * v1.z + w2 * v2.z;
            acc.w = acc.w * scl + w1 * v1.w + w2 * v2.w;
            m = newm;
        }
        for (; j < je; j++) {
            int s1 = srcA[j];
            const __half* kv = P640 + (size_t)s1 * 640 + 384;
            float4 k1 = ld4h(kv + c);
            float part = q4.x * k1.x + q4.y * k1.y + q4.z * k1.z + q4.w * k1.w;
            part += __shfl_xor_sync(0xffffffffu, part, 1);
            part += __shfl_xor_sync(0xffffffffu, part, 2);
            float a = part * pr;
            float newm = fmaxf(m, a);
            float scl = __expf(m - newm);
            float w = __expf(a - newm);
            s = s * scl + w;
            float4 v1 = ld4h(kv + 128 + c);
            acc.x = acc.x * scl + w * v1.x;
            acc.y = acc.y * scl + w * v1.y;
            acc.z = acc.z * scl + w * v1.z;
            acc.w = acc.w * scl + w * v1.w;
            m = newm;
        }
        float inv = 1.f / (s + 1e-16f);
        float4 r;
        float v;
        v = acc.x * inv; r.x = 0.5f * v * (1.f + erff(v * 0.70710678118654752f));
        v = acc.y * inv; r.y = 0.5f * v * (1.f + erff(v * 0.70710678118654752f));
        v = acc.z * inv; r.z = 0.5f * v * (1.f + erff(v * 0.70710678118654752f));
        v = acc.w * inv; r.w = 0.5f * v * (1.f + erff(v * 0.70710678118654752f));
        *(float4*)(aggA + (size_t)node * 128 + c) = r;
    }
}

// ---------------- BatchNorm (standalone; both node types per launch) ----------------
__global__ void bn_stats2(const float* __restrict__ hA, const float* __restrict__ hP,
                          float* __restrict__ stats)   // [0:256) author, [256:512) paper
{
    int c = threadIdx.x;
    const int nbA = (NA + 255) / 256;
    float s = 0.f, s2 = 0.f;
    if ((int)blockIdx.x < nbA) {
        int r0 = blockIdx.x * 256;
        int r1 = min(NA, r0 + 256);
        for (int r = r0; r < r1; r++) {
            float v = hA[(size_t)r * 128 + c];
            s += v; s2 += v * v;
        }
        atomicAdd(&stats[c], s);
        atomicAdd(&stats[128 + c], s2);
    } else {
        int r0 = (blockIdx.x - nbA) * 256;
        int r1 = min(NP, r0 + 256);
        for (int r = r0; r < r1; r++) {
            float v = hP[(size_t)r * 128 + c];
            s += v; s2 += v * v;
        }
        atomicAdd(&stats[256 + c], s);
        atomicAdd(&stats[256 + 128 + c], s2);
    }
}

__global__ void bn_apply2(const float* __restrict__ hA, const float* __restrict__ hP,
                          const float* __restrict__ stats,
                          const float* __restrict__ gamma, const float* __restrict__ beta,
                          float* __restrict__ outA, float* __restrict__ outP)
{
    int i = blockIdx.x * blockDim.x + threadIdx.x;
    const int totA = NA * 128;
    const int totP = NP * 128;
    if (i < totA) {
        int c = i & 127;
        float invN = 1.f / (float)NA;
        float mu = stats[c] * invN;
        float var = stats[128 + c] * invN - mu * mu;
        outA[i] = (hA[i] - mu) * rsqrtf(var + BN_EPS) * gamma[c] + beta[c];
    } else {
        int k = i - totA;
        if (k >= totP) return;
        int c = k & 127;
        float invN = 1.f / (float)NP;
        float mu = stats[256 + c] * invN;
        float var = stats[256 + 128 + c] * invN - mu * mu;
        outP[k] = (hP[k] - mu) * rsqrtf(var + BN_EPS) * gamma[c] + beta[c];
    }
}

// ---------------------------------------------------------------
static inline int cdiv(long long a, long long b) { return (int)((a + b - 1) / b); }

extern "C" void kernel_launch(void* const* d_in, const int* in_sizes, int n_in,
                              void* d_out, int out_size)
{
    const float* x_author = (const float*)d_in[0];
    const float* x_paper  = (const float*)d_in[1];
    const int* writes_src = (const int*)d_in[2];
    const int* writes_dst = (const int*)d_in[3];
    const int* rev_src    = (const int*)d_in[4];
    const int* rev_dst    = (const int*)d_in[5];
    const int* cites_src  = (const int*)d_in[6];
    const int* cites_dst  = (const int*)d_in[7];
    const float* linA_W   = (const float*)d_in[8];
    const float* linA_b   = (const float*)d_in[9];
    const float* linP_W   = (const float*)d_in[10];
    const float* linP_b   = (const float*)d_in[11];
    const float* kqv_W    = (const float*)d_in[12];
    const float* kqv_b    = (const float*)d_in[13];
    const float* a_k      = (const float*)d_in[14];
    const float* a_v      = (const float*)d_in[15];
    const float* p_rel    = (const float*)d_in[16];
    const float* out_W    = (const float*)d_in[17];
    const float* out_b    = (const float*)d_in[18];
    const float* skipP    = (const float*)d_in[19];
    const float* bn_gamma = (const float*)d_in[20];
    const float* bn_beta  = (const float*)d_in[21];

    float* base = nullptr;
    cudaGetSymbolAddress((void**)&base, g_scratch);

    float* XA    = base + OFF_XA;
    float* XP    = base + OFF_XP;
    __half* A384 = (__half*)(base + OFF_A384);
    __half* P640 = (__half*)(base + OFF_P640);
    float* AGGA  = base + OFF_AGGA;
    float* AGGP  = base + OFF_AGGP;
    float* TMPA  = base + OFF_TMPA;
    float* TMPP  = base + OFF_TMPP;
    float* WA    = base + OFF_WA;
    float* WP    = base + OFF_WP;
    float* WAB   = base + OFF_WAB;
    float* WPB   = base + OFF_WPB;
    float* STA   = base + OFF_STATS;        // [0:256) author, [256:512) paper
    int* ibase   = (int*)(base + OFF_INT);
    int* ROWP    = ibase + IOFF_ROWP;
    int* ROWA    = ibase + IOFF_ROWA;
    int* CURP    = ibase + IOFF_CURP;
    int* CURA    = ibase + IOFF_CURA;
    int* SRCP    = ibase + IOFF_SRCP;
    int* SRCA    = ibase + IOFF_SRCA;
    int* BS      = ibase + IOFF_BS;

    const int myA = cdiv(NA, 128);   // 391
    const int myP = cdiv(NP, 128);   // 782

    // -------- CSR build + composite weights (x-independent) --------
    const int nbP = cdiv(NP, 1024), nbA = cdiv(NA, 1024);
    cudaMemsetAsync(CURP, 0, (size_t)NP * 4, 0);
    cudaMemsetAsync(CURA, 0, (size_t)NA * 4, 0);
    hist_kernel<<<cdiv(EW, 256), 256>>>(writes_dst, CURP, EW);
    hist_kernel<<<cdiv(EC, 256), 256>>>(cites_dst, CURP, EC);
    hist_kernel<<<cdiv(ER, 256), 256>>>(rev_dst, CURA, ER);
    scan_partial<<<nbP, 256>>>(CURP, ROWP, BS, NP);
    scan_small<<<1, 256>>>(BS, nbP);
    add_off<<<cdiv(NP, 256), 256>>>(ROWP, CURP, BS, NP, nbP);
    scan_partial<<<nbA, 256>>>(CURA, ROWA, BS, NA);
    scan_small<<<1, 256>>>(BS, nbA);
    add_off<<<cdiv(NA, 256), 256>>>(ROWA, CURA, BS, NA, nbA);
    scatter_kernel<<<cdiv(EW, 256), 256>>>(writes_src, writes_dst, CURP, SRCP, EW, 0);
    scatter_kernel<<<cdiv(EC, 256), 256>>>(cites_src, cites_dst, CURP, SRCP, EC, NA);
    scatter_kernel<<<cdiv(ER, 256), 256>>>(rev_src, rev_dst, CURA, SRCA, ER, 0);
    wcompA<<<cdiv(2 * 128 * 384, 256), 256>>>(kqv_W, a_k, a_v, WA);
    wcompP<<<cdiv(2 * 128 * 640, 256), 256>>>(kqv_W, a_k, a_v, WP);
    bcompA<<<3, 256>>>(kqv_b, a_k, a_v, WAB);
    bcompP<<<5, 256>>>(kqv_b, a_k, a_v, WPB);

    // -------- input projections + relu (merged pair) --------
    gemm2<<<dim3(1, myA + myP), 256>>>(
        x_author, 128, linA_W, 128, linA_b, XA, nullptr, 128, NA, 1, nullptr, nullptr,
        x_paper,  128, linP_W, 128, linP_b, XP, nullptr, 128, NP, 1, nullptr, nullptr,
        myA, 1);

    for (int l = 0; l < 2; l++) {
        // merged Q|K|V projections, fp16 output (merged pair; author gx=3, paper gx=5)
        gemm2<<<dim3(5, myA + myP), 256>>>(
            XA, 128, WA + (size_t)l * 128 * 384, 384, WAB + (size_t)l * 384,
            nullptr, A384, 384, NA, 3, nullptr, nullptr,
            XP, 128, WP + (size_t)l * 128 * 640, 640, WPB + (size_t)l * 640,
            nullptr, P640, 640, NP, 5, nullptr, nullptr,
            myA, 0);

        // fused attention + softmax + aggregation + gelu (single launch, both types)
        attn_agg2<<<cdiv((long long)(NP + NA) * 32, 256), 256>>>(
            A384, P640,
            ROWP, SRCP, p_rel + (size_t)(l * 3 + 0) * NH, p_rel + (size_t)(l * 3 + 2) * NH,
            ROWA, SRCA, p_rel + (size_t)(l * 3 + 1) * NH,
            AGGP, AGGA);

        // output projection + fused sigmoid-skip mix (merged pair)
        gemm2<<<dim3(1, myA + myP), 256>>>(
            AGGA, 128, out_W + (size_t)(l * 2 + 0) * 128 * 128, 128, out_b + (size_t)(l * 2 + 0) * 128,
            TMPA, nullptr, 128, NA, 1, XA, skipP + (l * 2 + 0),
            AGGP, 128, out_W + (size_t)(l * 2 + 1) * 128 * 128, 128, out_b + (size_t)(l * 2 + 1) * 128,
            TMPP, nullptr, 128, NP, 1, XP, skipP + (l * 2 + 1),
            myA, 2);

        // batch norm: stats then apply, both node types per launch
        cudaMemsetAsync(STA, 0, 512 * 4, 0);
        bn_stats2<<<cdiv(NA, 256) + cdiv(NP, 256), 128>>>(TMPA, TMPP, STA);
        float* outA = (l == 1) ? (float*)d_out : XA;
        float* outP = (l == 1) ? (float*)d_out + (size_t)NA * 128 : XP;
        bn_apply2<<<cdiv((long long)(NA + NP) * 128, 256), 256>>>(TMPA, TMPP, STA,
                                                                  bn_gamma + (size_t)l * 128,
                                                                  bn_beta + (size_t)l * 128,
                                                                  outA, outP);
    }
}